// round 1
// baseline (speedup 1.0000x reference)
#include <cuda_runtime.h>

#define NH 12
#define HD 64
#define NT 197
#define BB 64
#define EE 768
#define MT (BB*NT)      // 12608
#define TROWS 30
#define GRID14 14

// scratch (static device memory; allocation-free)
__device__ float g_q[MT*EE];    // [(b*12+h)*197 + n]*64 + d
__device__ float g_k[MT*EE];
__device__ float g_v[MT*EE];
__device__ float g_ctx[MT*EE];  // [b*197+n][h*64+d]

// ---------------------------------------------------------------------------
// SIMT fp32 GEMM: C[M x Ncols] = A[M x 768] @ B[768 x Ncols]
// MODE 0: A = x, B in {wq,wk,wv} selected per 768-col band, scatter to g_q/k/v
// MODE 1: A = g_ctx, B = wproj, C = out + bias
// BM=BN=128, BK=8, 256 threads, 8x8 per thread
// ---------------------------------------------------------------------------
template<int MODE>
__global__ __launch_bounds__(256, 2)
void gemm_k(const float* __restrict__ A,
            const float* __restrict__ B0, const float* __restrict__ B1,
            const float* __restrict__ B2, const float* __restrict__ bias,
            float* __restrict__ Cout)
{
    __shared__ float As[8][128];
    __shared__ float Bs[8][128];

    const int tid = threadIdx.x;
    const int m0 = blockIdx.y * 128;
    const int n0 = blockIdx.x * 128;

    const float* Ap = (MODE == 0) ? A : g_ctx;
    const float* Bp;
    int bcol0, which = 0;
    if (MODE == 0) {
        which = n0 / EE;                       // tile never straddles (768 % 128 == 0)
        Bp = (which == 0) ? B0 : (which == 1) ? B1 : B2;
        bcol0 = n0 - which * EE;
    } else {
        Bp = B0; bcol0 = n0;
    }

    const int arow = tid >> 1, acol = (tid & 1) * 4;
    const int brow = tid >> 5, bcol = (tid & 31) * 4;
    const int ti = tid >> 4, tj = tid & 15;

    float acc[8][8];
#pragma unroll
    for (int i = 0; i < 8; i++)
#pragma unroll
        for (int j = 0; j < 8; j++) acc[i][j] = 0.f;

    const int gmA = m0 + arow;
    const bool aok = gmA < MT;
    const float* aptr = Ap + (size_t)(aok ? gmA : 0) * EE + acol;
    const float* bptr = Bp + (size_t)brow * EE + bcol0 + bcol;

    for (int kt = 0; kt < EE; kt += 8) {
        float4 av = aok ? *(const float4*)(aptr + kt) : make_float4(0.f,0.f,0.f,0.f);
        float4 bv = *(const float4*)(bptr + (size_t)kt * EE);
        As[acol+0][arow] = av.x; As[acol+1][arow] = av.y;
        As[acol+2][arow] = av.z; As[acol+3][arow] = av.w;
        *(float4*)&Bs[brow][bcol] = bv;
        __syncthreads();
#pragma unroll
        for (int k = 0; k < 8; k++) {
            float a[8], b[8];
            *(float4*)&a[0] = *(const float4*)&As[k][ti*8];
            *(float4*)&a[4] = *(const float4*)&As[k][ti*8+4];
            *(float4*)&b[0] = *(const float4*)&Bs[k][tj*8];
            *(float4*)&b[4] = *(const float4*)&Bs[k][tj*8+4];
#pragma unroll
            for (int i = 0; i < 8; i++)
#pragma unroll
                for (int j = 0; j < 8; j++) acc[i][j] += a[i]*b[j];
        }
        __syncthreads();
    }

#pragma unroll
    for (int mi = 0; mi < 8; mi++) {
        int gm = m0 + ti*8 + mi;
        if (gm >= MT) continue;
        if (MODE == 1) {
            int nc = n0 + tj*8;
            float* dst = Cout + (size_t)gm * EE + nc;
            float4 o0 = make_float4(acc[mi][0]+bias[nc+0], acc[mi][1]+bias[nc+1],
                                    acc[mi][2]+bias[nc+2], acc[mi][3]+bias[nc+3]);
            float4 o1 = make_float4(acc[mi][4]+bias[nc+4], acc[mi][5]+bias[nc+5],
                                    acc[mi][6]+bias[nc+6], acc[mi][7]+bias[nc+7]);
            *(float4*)dst = o0; *(float4*)(dst+4) = o1;
        } else {
            int b = gm / NT, n = gm - b*NT;
            int c = bcol0 + tj*8;       // 8-aligned: stays within one 64-wide head
            int h = c >> 6, d = c & 63;
            float* base = (which == 0) ? g_q : (which == 1) ? g_k : g_v;
            float* dst = base + (((size_t)(b*NH + h))*NT + n)*HD + d;
            *(float4*)dst     = make_float4(acc[mi][0],acc[mi][1],acc[mi][2],acc[mi][3]);
            *(float4*)(dst+4) = make_float4(acc[mi][4],acc[mi][5],acc[mi][6],acc[mi][7]);
        }
    }
}

// ---------------------------------------------------------------------------
// Fused attention: one CTA per (b,h). Extended-J trick:
//   cols 0..196 = K,  197..226 = rk_v,  227..256 = rk_h  (score GEMM)
//   rows 0..196 = V,  197..226 = rv_v,  227..256 = rv_h  (PV GEMM)
// Softmax pass converts raw scores + qr-terms -> probs, then writes the
// 60 rel-pos mass bins into P_ext cols 197..256 (14 row-sums/14 col-sums).
// ---------------------------------------------------------------------------
#define IB 32
#define JX 257
#define KS_LD 264
#define S_LD 261
#define QS_LD 65
#define SM_KS (64*KS_LD)
#define SM_VS (JX*64)
#define SM_S  (IB*S_LD)
#define SM_QS (IB*QS_LD)
#define ATT_SMEM_BYTES ((SM_KS + SM_VS + SM_S + SM_QS) * 4)

__global__ __launch_bounds__(256, 1)
void attn_k(const float* __restrict__ rk_v, const float* __restrict__ rk_h,
            const float* __restrict__ rv_v, const float* __restrict__ rv_h)
{
    extern __shared__ float sm[];
    float* ks = sm;                 // [64][KS_LD], transposed K_ext
    float* vs = ks + SM_KS;         // [JX][64], V_ext
    float* S  = vs + SM_VS;         // [IB][S_LD], scores / P_ext
    float* qs = S + SM_S;           // [IB][QS_LD]

    const int bh = blockIdx.x;
    const int tid = threadIdx.x;
    const int w = tid >> 5, lane = tid & 31;
    const int b = bh / NH, h = bh - b*NH;
    const float* Kb = g_k + (size_t)bh * NT * HD;
    const float* Vb = g_v + (size_t)bh * NT * HD;
    const float* Qb = g_q + (size_t)bh * NT * HD;

    // zero K_ext padding, then fill
    for (int i = tid; i < SM_KS; i += 256) ks[i] = 0.f;
    __syncthreads();
    for (int i = tid; i < NT*HD; i += 256) {
        int j = i >> 6, d = i & 63;
        ks[d*KS_LD + j] = Kb[i];
    }
    for (int i = tid; i < TROWS*HD; i += 256) {
        int t = i >> 6, d = i & 63;
        ks[d*KS_LD + 197 + t] = rk_v[i];
        ks[d*KS_LD + 227 + t] = rk_h[i];
    }
    for (int i = tid; i < NT*HD; i += 256) vs[i] = Vb[i];
    for (int i = tid; i < TROWS*HD; i += 256) {
        vs[197*64 + i] = rv_v[i];
        vs[227*64 + i] = rv_h[i];
    }
    __syncthreads();

    for (int i0 = 0; i0 < NT; i0 += IB) {
        // load Q block
        for (int i = tid; i < IB*HD; i += 256) {
            int r = i >> 6, d = i & 63;
            int gi = i0 + r;
            qs[r*QS_LD + d] = (gi < NT) ? Qb[gi*HD + d] : 0.f;
        }
        __syncthreads();

        // score GEMM: S[IB][257] = qs @ ks ; lane = i-row, warp owns 8-col slices
        {
            const float* qrow = qs + lane*QS_LD;
            for (int j0 = w*8; j0 < JX; j0 += 64) {
                float acc0=0,acc1=0,acc2=0,acc3=0,acc4=0,acc5=0,acc6=0,acc7=0;
#pragma unroll 8
                for (int kd = 0; kd < 64; kd++) {
                    float qv = qrow[kd];
                    const float* kr = ks + kd*KS_LD + j0;
                    float4 b0 = *(const float4*)kr;
                    float4 b1 = *(const float4*)(kr+4);
                    acc0 += qv*b0.x; acc1 += qv*b0.y; acc2 += qv*b0.z; acc3 += qv*b0.w;
                    acc4 += qv*b1.x; acc5 += qv*b1.y; acc6 += qv*b1.z; acc7 += qv*b1.w;
                }
                float* srow = S + lane*S_LD + j0;
                float a[8] = {acc0,acc1,acc2,acc3,acc4,acc5,acc6,acc7};
#pragma unroll
                for (int jj = 0; jj < 8; jj++)
                    if (j0 + jj < JX) srow[jj] = a[jj];
            }
        }
        __syncthreads();

        // softmax + rel-pos bins: warp w handles rows w*4 .. w*4+3
        for (int rr = 0; rr < 4; rr++) {
            int r = w*4 + rr;
            int gi = i0 + r;
            if (gi >= NT) continue;
            float* srow = S + r*S_LD;
            int gvi = (gi > 0) ? (gi-1) / GRID14 : 0;
            int ghi = (gi > 0) ? (gi-1) % GRID14 : 0;

            float sv[7];
            float mx = -1e30f;
#pragma unroll
            for (int jj = 0; jj < 7; jj++) {
                int j = lane + jj*32;
                float s = -1e30f;
                if (j < NT) {
                    int tv = 0, th = 0;
                    if (gi > 0 && j > 0) {
                        tv = (j-1)/GRID14 - gvi + 15;
                        th = (j-1)%GRID14 - ghi + 15;
                    }
                    s = (srow[j] + srow[197+tv] + srow[227+th]) * 0.125f;
                }
                sv[jj] = s;
                mx = fmaxf(mx, s);
            }
#pragma unroll
            for (int o = 16; o > 0; o >>= 1) mx = fmaxf(mx, __shfl_xor_sync(0xFFFFFFFFu, mx, o));
            float sum = 0.f;
#pragma unroll
            for (int jj = 0; jj < 7; jj++) { float e = __expf(sv[jj]-mx); sv[jj] = e; sum += e; }
#pragma unroll
            for (int o = 16; o > 0; o >>= 1) sum += __shfl_xor_sync(0xFFFFFFFFu, sum, o);
            float inv = 1.f / sum;
#pragma unroll
            for (int jj = 0; jj < 7; jj++) {
                int j = lane + jj*32;
                if (j < NT) srow[j] = sv[jj]*inv;
            }
            __syncwarp();
            if (lane < TROWS) { srow[197+lane] = 0.f; srow[227+lane] = 0.f; }
            __syncwarp();
            if (gi == 0) {
                if (lane == 0) { srow[197] = 1.f; srow[227] = 1.f; }
            } else {
                if (lane < 14) {                       // grid-row sums -> wv bins
                    float R = 0.f;
#pragma unroll
                    for (int c = 0; c < 14; c++) R += srow[1 + lane*14 + c];
                    srow[197 + (lane - gvi + 15)] = R;
                } else if (lane == 14) {               // CLS mass -> bin 0
                    float p0 = srow[0];
                    srow[197] = p0; srow[227] = p0;
                } else if (lane >= 16 && lane < 30) {  // grid-col sums -> wh bins
                    int c = lane - 16;
                    float Cc = 0.f;
#pragma unroll
                    for (int g = 0; g < 14; g++) Cc += srow[1 + g*14 + c];
                    srow[227 + (c - ghi + 15)] = Cc;
                }
            }
            __syncwarp();
        }
        __syncthreads();

        // PV GEMM: out[IB][64] = P_ext @ V_ext ; lane = i-row, warp owns 8 d-cols
        {
            float acc0=0,acc1=0,acc2=0,acc3=0,acc4=0,acc5=0,acc6=0,acc7=0;
            const int dbase = w*8;
            const float* prow = S + lane*S_LD;
#pragma unroll 4
            for (int jp = 0; jp < JX; jp++) {
                float p = prow[jp];
                float4 v0 = *(const float4*)(vs + jp*64 + dbase);
                float4 v1 = *(const float4*)(vs + jp*64 + dbase + 4);
                acc0 += p*v0.x; acc1 += p*v0.y; acc2 += p*v0.z; acc3 += p*v0.w;
                acc4 += p*v1.x; acc5 += p*v1.y; acc6 += p*v1.z; acc7 += p*v1.w;
            }
            int gi = i0 + lane;
            if (gi < NT) {
                float* dst = g_ctx + ((size_t)(b*NT + gi))*EE + h*HD + dbase;
                *(float4*)dst     = make_float4(acc0,acc1,acc2,acc3);
                *(float4*)(dst+4) = make_float4(acc4,acc5,acc6,acc7);
            }
        }
        __syncthreads();
    }
}

// ---------------------------------------------------------------------------
extern "C" void kernel_launch(void* const* d_in, const int* in_sizes, int n_in,
                              void* d_out, int out_size)
{
    const float* x     = (const float*)d_in[0];
    const float* wq    = (const float*)d_in[1];
    const float* wk    = (const float*)d_in[2];
    const float* wv    = (const float*)d_in[3];
    const float* wproj = (const float*)d_in[4];
    const float* bproj = (const float*)d_in[5];
    const float* rk_v  = (const float*)d_in[6];
    const float* rk_h  = (const float*)d_in[7];
    const float* rv_v  = (const float*)d_in[8];
    const float* rv_h  = (const float*)d_in[9];
    float* out = (float*)d_out;

    cudaFuncSetAttribute(attn_k, cudaFuncAttributeMaxDynamicSharedMemorySize,
                         ATT_SMEM_BYTES);

    dim3 g1(3*EE/128, (MT + 127)/128);
    gemm_k<0><<<g1, 256>>>(x, wq, wk, wv, nullptr, nullptr);

    attn_k<<<BB*NH, 256, ATT_SMEM_BYTES>>>(rk_v, rk_h, rv_v, rv_h);

    dim3 g2(EE/128, (MT + 127)/128);
    gemm_k<1><<<g2, 256>>>(nullptr, wproj, nullptr, nullptr, bproj, out);
}

// round 9
// speedup vs baseline: 1.6527x; 1.6527x over previous
#include <cuda_runtime.h>
#include <cuda_fp16.h>
#include <cstdint>

#define NH 12
#define HD 64
#define NT 197
#define BB 64
#define EE 768
#define MT (BB*NT)      // 12608
#define TROWS 30
#define GRID14 14

// scratch (static device memory; allocation-free) — identical set to round 1
__device__ __align__(16) float g_q[MT*EE];    // [(b*12+h)*197 + n]*64 + d
__device__ __align__(16) float g_k[MT*EE];
__device__ __align__(16) float g_v[MT*EE];
__device__ __align__(16) float g_ctx[MT*EE];  // [b*197+n][h*64+d]

// ===========================================================================
// helpers — value-returning asm only; no references, no struct out-params
// ===========================================================================
__device__ __forceinline__ uint32_t smem_u32(const void* p) {
    uint32_t a;
    asm("{ .reg .u64 t; cvta.to.shared.u64 t, %1; cvt.u32.u64 %0, t; }" : "=r"(a) : "l"(p));
    return a;
}
// pack two f32 into f16x2 word: lo at low half, hi at high half
__device__ __forceinline__ uint32_t f2h2(float lo, float hi_) {
    uint32_t r;
    asm("cvt.rn.f16x2.f32 %0, %1, %2;" : "=r"(r) : "f"(hi_), "f"(lo));
    return r;
}
// round f32 through f16 and back (for residual computation)
__device__ __forceinline__ float rn16(float x) {
    float r;
    asm("{ .reg .f16 t; cvt.rn.f16.f32 t, %1; cvt.f32.f16 %0, t; }" : "=f"(r) : "f"(x));
    return r;
}
#define LDSM4(r0,r1,r2,r3,addr) \
    asm volatile("ldmatrix.sync.aligned.m8n8.x4.shared.b16 {%0,%1,%2,%3}, [%4];" \
                 : "=r"(r0), "=r"(r1), "=r"(r2), "=r"(r3) : "r"(addr))
#define LDSM4T(r0,r1,r2,r3,addr) \
    asm volatile("ldmatrix.sync.aligned.m8n8.x4.trans.shared.b16 {%0,%1,%2,%3}, [%4];" \
                 : "=r"(r0), "=r"(r1), "=r"(r2), "=r"(r3) : "r"(addr))
#define MMA_S(d0,d1,d2,d3, a0,a1,a2,a3, b0,b1) \
    asm volatile("mma.sync.aligned.m16n8k16.row.col.f32.f16.f16.f32 " \
                 "{%0,%1,%2,%3}, {%4,%5,%6,%7}, {%8,%9}, {%0,%1,%2,%3};" \
                 : "+f"(d0), "+f"(d1), "+f"(d2), "+f"(d3) \
                 : "r"(a0), "r"(a1), "r"(a2), "r"(a3), "r"(b0), "r"(b1))

// ===========================================================================
// mma.sync fp16 3-product GEMM with IN-KERNEL hi/lo split.
// C[M x NCOLS] = A[M x 768] @ B[768 x NCOLS], fp32 in, fp32 out.
// CTA 128x128, 8 warps (2m x 4n), warp tile 64x32, BK=32, dbl-buffered smem.
// Ah/Al smem: [128][40] half. Bh/Bl smem: [32][136] half (k-major).
// MODE 0: NCOLS=2304 over {wq,wk,wv}, scatter -> g_q/g_k/g_v.
// MODE 1: NCOLS=768 (wproj), C = acc + bias -> out.
// ===========================================================================
#define A_STRIDE 40            // halves; 80 B row (16B-aligned)
#define B_STRIDE 136           // halves; 272 B row (16B-aligned)
#define OFF_AL 10240           // 128*40*2
#define OFF_BH 20480
#define OFF_BL 29184           // OFF_BH + 32*136*2
#define GEMM_STG 37888
#define GEMM_SMEM (2*GEMM_STG)

#define DECL_ACC(m,n) \
    float c##m##n##_0 = 0.f, c##m##n##_1 = 0.f, c##m##n##_2 = 0.f, c##m##n##_3 = 0.f

#define MMA3(m,n, B0,B1, C0,C1) \
    MMA_S(c##m##n##_0,c##m##n##_1,c##m##n##_2,c##m##n##_3, \
          ah##m##_0,ah##m##_1,ah##m##_2,ah##m##_3, B0,B1); \
    MMA_S(c##m##n##_0,c##m##n##_1,c##m##n##_2,c##m##n##_3, \
          ah##m##_0,ah##m##_1,ah##m##_2,ah##m##_3, C0,C1); \
    MMA_S(c##m##n##_0,c##m##n##_1,c##m##n##_2,c##m##n##_3, \
          al##m##_0,al##m##_1,al##m##_2,al##m##_3, B0,B1)

#define LDA(m, addr_) \
    LDSM4(ah##m##_0,ah##m##_1,ah##m##_2,ah##m##_3, (addr_)); \
    LDSM4(al##m##_0,al##m##_1,al##m##_2,al##m##_3, (addr_) + OFF_AL)

#define KSTEP(ks_) do { \
    uint32_t ah0_0,ah0_1,ah0_2,ah0_3, ah1_0,ah1_1,ah1_2,ah1_3; \
    uint32_t ah2_0,ah2_1,ah2_2,ah2_3, ah3_0,ah3_1,ah3_2,ah3_3; \
    uint32_t al0_0,al0_1,al0_2,al0_3, al1_0,al1_1,al1_2,al1_3; \
    uint32_t al2_0,al2_1,al2_2,al2_3, al3_0,al3_1,al3_2,al3_3; \
    uint32_t bh0_0,bh0_1,bh0_2,bh0_3, bh1_0,bh1_1,bh1_2,bh1_3; \
    uint32_t bl0_0,bl0_1,bl0_2,bl0_3, bl1_0,bl1_1,bl1_2,bl1_3; \
    uint32_t a0_ = stg + (uint32_t)((wm0 + r15) * A_STRIDE + (ks_)*16 + h16*8) * 2; \
    LDA(0, a0_); \
    LDA(1, a0_ + (uint32_t)(16 * A_STRIDE * 2)); \
    LDA(2, a0_ + (uint32_t)(32 * A_STRIDE * 2)); \
    LDA(3, a0_ + (uint32_t)(48 * A_STRIDE * 2)); \
    uint32_t b0_ = stg + OFF_BH + (uint32_t)(((ks_)*16 + r15) * B_STRIDE + wn0 + h16*8) * 2; \
    uint32_t b1_ = b0_ + 32; \
    LDSM4T(bh0_0,bh0_1,bh0_2,bh0_3, b0_); \
    LDSM4T(bh1_0,bh1_1,bh1_2,bh1_3, b1_); \
    LDSM4T(bl0_0,bl0_1,bl0_2,bl0_3, b0_ + (OFF_BL - OFF_BH)); \
    LDSM4T(bl1_0,bl1_1,bl1_2,bl1_3, b1_ + (OFF_BL - OFF_BH)); \
    MMA3(0,0, bh0_0,bh0_1, bl0_0,bl0_1); \
    MMA3(0,1, bh0_2,bh0_3, bl0_2,bl0_3); \
    MMA3(0,2, bh1_0,bh1_1, bl1_0,bl1_1); \
    MMA3(0,3, bh1_2,bh1_3, bl1_2,bl1_3); \
    MMA3(1,0, bh0_0,bh0_1, bl0_0,bl0_1); \
    MMA3(1,1, bh0_2,bh0_3, bl0_2,bl0_3); \
    MMA3(1,2, bh1_0,bh1_1, bl1_0,bl1_1); \
    MMA3(1,3, bh1_2,bh1_3, bl1_2,bl1_3); \
    MMA3(2,0, bh0_0,bh0_1, bl0_0,bl0_1); \
    MMA3(2,1, bh0_2,bh0_3, bl0_2,bl0_3); \
    MMA3(2,2, bh1_0,bh1_1, bl1_0,bl1_1); \
    MMA3(2,3, bh1_2,bh1_3, bl1_2,bl1_3); \
    MMA3(3,0, bh0_0,bh0_1, bl0_0,bl0_1); \
    MMA3(3,1, bh0_2,bh0_3, bl0_2,bl0_3); \
    MMA3(3,2, bh1_0,bh1_1, bl1_0,bl1_1); \
    MMA3(3,3, bh1_2,bh1_3, bl1_2,bl1_3); \
} while(0)

// global->register loads (fp32, R1-proven pattern)
#define LDA4(dst, i_, k0_) do { \
    int row_ = (i_) >> 3, c4_ = (i_) & 7; int gm_ = m0 + row_; \
    dst = (gm_ < MT) ? *(const float4*)(Ap + (size_t)gm_ * EE + (k0_) + c4_ * 4) \
                     : make_float4(0.f, 0.f, 0.f, 0.f); \
} while(0)
#define LDB4(dst, i_, k0_) do { \
    int kr_ = (i_) >> 5, c4_ = (i_) & 31; \
    dst = *(const float4*)(Bp + (size_t)((k0_) + kr_) * EE + bcol0 + c4_ * 4); \
} while(0)
#define LDG_CHUNK(k0_) do { \
    LDA4(fa0, tid,       (k0_)); LDA4(fa1, tid + 256, (k0_)); \
    LDA4(fa2, tid + 512, (k0_)); LDA4(fa3, tid + 768, (k0_)); \
    LDB4(fb0, tid,       (k0_)); LDB4(fb1, tid + 256, (k0_)); \
    LDB4(fb2, tid + 512, (k0_)); LDB4(fb3, tid + 768, (k0_)); \
} while(0)

// convert (hi/lo split) + store to smem; value-returning asm only
#define STS_A1(fv, i_) do { \
    int row_ = (i_) >> 3, c4_ = (i_) & 7; \
    uint32_t h01_ = f2h2(fv.x, fv.y), h23_ = f2h2(fv.z, fv.w); \
    uint32_t l01_ = f2h2(fv.x - rn16(fv.x), fv.y - rn16(fv.y)); \
    uint32_t l23_ = f2h2(fv.z - rn16(fv.z), fv.w - rn16(fv.w)); \
    char* p_ = stgp + row_ * (A_STRIDE * 2) + c4_ * 8; \
    *(uint2*)p_ = make_uint2(h01_, h23_); \
    *(uint2*)(p_ + OFF_AL) = make_uint2(l01_, l23_); \
} while(0)
#define STS_B1(fv, i_) do { \
    int kr_ = (i_) >> 5, c4_ = (i_) & 31; \
    uint32_t h01_ = f2h2(fv.x, fv.y), h23_ = f2h2(fv.z, fv.w); \
    uint32_t l01_ = f2h2(fv.x - rn16(fv.x), fv.y - rn16(fv.y)); \
    uint32_t l23_ = f2h2(fv.z - rn16(fv.z), fv.w - rn16(fv.w)); \
    char* p_ = stgp + OFF_BH + kr_ * (B_STRIDE * 2) + c4_ * 8; \
    *(uint2*)p_ = make_uint2(h01_, h23_); \
    *(uint2*)(p_ + (OFF_BL - OFF_BH)) = make_uint2(l01_, l23_); \
} while(0)

#define STORE2(r_, col_, v0, v1) do { \
    if (MODE == 1) { \
        float2 o_; o_.x = (v0) + bias[(col_)]; o_.y = (v1) + bias[(col_)+1]; \
        *(float2*)(Cout + (size_t)(r_) * EE + (col_)) = o_; \
    } else { \
        int bb_ = (r_) / NT, nn_ = (r_) - bb_ * NT; \
        int which_ = (col_) / EE, cc_ = (col_) - which_ * EE; \
        int hh_ = cc_ >> 6, dd_ = cc_ & 63; \
        float* bp_ = (which_ == 0) ? g_q : (which_ == 1) ? g_k : g_v; \
        *(float2*)(bp_ + (((size_t)(bb_ * NH + hh_)) * NT + nn_) * HD + dd_) = \
            make_float2((v0), (v1)); \
    } \
} while(0)

#define STORE_TILE(m,n) do { \
    int r_ = m0 + wm0 + (m)*16 + (lane >> 2); \
    int cb_ = n0 + wn0 + (n)*8 + (lane & 3) * 2; \
    if (r_ < MT)     STORE2(r_,     cb_, c##m##n##_0, c##m##n##_1); \
    if (r_ + 8 < MT) STORE2(r_ + 8, cb_, c##m##n##_2, c##m##n##_3); \
} while(0)

template<int MODE>
__global__ __launch_bounds__(256, 1)
void gemm_mma(const float* __restrict__ A,
              const float* __restrict__ B0, const float* __restrict__ B1,
              const float* __restrict__ B2, const float* __restrict__ bias,
              float* __restrict__ Cout)
{
    extern __shared__ char smem_raw[];
    const uint32_t sb = smem_u32(smem_raw);
    const int tid = threadIdx.x;
    const int lane = tid & 31, wid = tid >> 5;
    const int m0 = blockIdx.y * 128, n0 = blockIdx.x * 128;
    const int wm0 = (wid >> 2) * 64, wn0 = (wid & 3) * 32;
    const int r15 = lane & 15, h16 = lane >> 4;

    const float* Ap = (MODE == 0) ? A : g_ctx;
    const float* Bp;
    int bcol0;
    if (MODE == 0) {
        int which = n0 / EE;                    // tile never straddles
        Bp = (which == 0) ? B0 : (which == 1) ? B1 : B2;
        bcol0 = n0 - which * EE;
    } else { Bp = B0; bcol0 = n0; }

    DECL_ACC(0,0); DECL_ACC(0,1); DECL_ACC(0,2); DECL_ACC(0,3);
    DECL_ACC(1,0); DECL_ACC(1,1); DECL_ACC(1,2); DECL_ACC(1,3);
    DECL_ACC(2,0); DECL_ACC(2,1); DECL_ACC(2,2); DECL_ACC(2,3);
    DECL_ACC(3,0); DECL_ACC(3,1); DECL_ACC(3,2); DECL_ACC(3,3);

    float4 fa0, fa1, fa2, fa3, fb0, fb1, fb2, fb3;
    LDG_CHUNK(0);

    const int NC = 24;
#pragma unroll 1
    for (int c = 0; c < NC; c++) {
        {
            char* stgp = smem_raw + (c & 1) * GEMM_STG;
            STS_A1(fa0, tid);       STS_A1(fa1, tid + 256);
            STS_A1(fa2, tid + 512); STS_A1(fa3, tid + 768);
            STS_B1(fb0, tid);       STS_B1(fb1, tid + 256);
            STS_B1(fb2, tid + 512); STS_B1(fb3, tid + 768);
        }
        __syncthreads();
        if (c + 1 < NC) LDG_CHUNK((c + 1) * 32);   // overlap next loads w/ compute
        const uint32_t stg = sb + (c & 1) * GEMM_STG;
        KSTEP(0);
        KSTEP(1);
        __syncthreads();
    }

    STORE_TILE(0,0); STORE_TILE(0,1); STORE_TILE(0,2); STORE_TILE(0,3);
    STORE_TILE(1,0); STORE_TILE(1,1); STORE_TILE(1,2); STORE_TILE(1,3);
    STORE_TILE(2,0); STORE_TILE(2,1); STORE_TILE(2,2); STORE_TILE(2,3);
    STORE_TILE(3,0); STORE_TILE(3,1); STORE_TILE(3,2); STORE_TILE(3,3);
}

// ---------------------------------------------------------------------------
// Fused attention: byte-identical to the round-1 passing version.
// ---------------------------------------------------------------------------
#define IB 32
#define JX 257
#define KS_LD 264
#define S_LD 261
#define QS_LD 65
#define SM_KS (64*KS_LD)
#define SM_VS (JX*64)
#define SM_S  (IB*S_LD)
#define SM_QS (IB*QS_LD)
#define ATT_SMEM_BYTES ((SM_KS + SM_VS + SM_S + SM_QS) * 4)

__global__ __launch_bounds__(256, 1)
void attn_k(const float* __restrict__ rk_v, const float* __restrict__ rk_h,
            const float* __restrict__ rv_v, const float* __restrict__ rv_h)
{
    extern __shared__ float sm[];
    float* ks = sm;                 // [64][KS_LD], transposed K_ext
    float* vs = ks + SM_KS;         // [JX][64], V_ext
    float* S  = vs + SM_VS;         // [IB][S_LD], scores / P_ext
    float* qs = S + SM_S;           // [IB][QS_LD]

    const int bh = blockIdx.x;
    const int tid = threadIdx.x;
    const int w = tid >> 5, lane = tid & 31;
    const int b = bh / NH, h = bh - b*NH;
    const float* Kb = g_k + (size_t)bh * NT * HD;
    const float* Vb = g_v + (size_t)bh * NT * HD;
    const float* Qb = g_q + (size_t)bh * NT * HD;

    for (int i = tid; i < SM_KS; i += 256) ks[i] = 0.f;
    __syncthreads();
    for (int i = tid; i < NT*HD; i += 256) {
        int j = i >> 6, d = i & 63;
        ks[d*KS_LD + j] = Kb[i];
    }
    for (int i = tid; i < TROWS*HD; i += 256) {
        int t = i >> 6, d = i & 63;
        ks[d*KS_LD + 197 + t] = rk_v[i];
        ks[d*KS_LD + 227 + t] = rk_h[i];
    }
    for (int i = tid; i < NT*HD; i += 256) vs[i] = Vb[i];
    for (int i = tid; i < TROWS*HD; i += 256) {
        vs[197*64 + i] = rv_v[i];
        vs[227*64 + i] = rv_h[i];
    }
    __syncthreads();

    for (int i0 = 0; i0 < NT; i0 += IB) {
        for (int i = tid; i < IB*HD; i += 256) {
            int r = i >> 6, d = i & 63;
            int gi = i0 + r;
            qs[r*QS_LD + d] = (gi < NT) ? Qb[gi*HD + d] : 0.f;
        }
        __syncthreads();

        {
            const float* qrow = qs + lane*QS_LD;
            for (int j0 = w*8; j0 < JX; j0 += 64) {
                float acc0=0,acc1=0,acc2=0,acc3=0,acc4=0,acc5=0,acc6=0,acc7=0;
#pragma unroll 8
                for (int kd = 0; kd < 64; kd++) {
                    float qv = qrow[kd];
                    const float* kr = ks + kd*KS_LD + j0;
                    float4 b0 = *(const float4*)kr;
                    float4 b1 = *(const float4*)(kr+4);
                    acc0 += qv*b0.x; acc1 += qv*b0.y; acc2 += qv*b0.z; acc3 += qv*b0.w;
                    acc4 += qv*b1.x; acc5 += qv*b1.y; acc6 += qv*b1.z; acc7 += qv*b1.w;
                }
                float* srow = S + lane*S_LD + j0;
                float a[8] = {acc0,acc1,acc2,acc3,acc4,acc5,acc6,acc7};
#pragma unroll
                for (int jj = 0; jj < 8; jj++)
                    if (j0 + jj < JX) srow[jj] = a[jj];
            }
        }
        __syncthreads();

        for (int rr = 0; rr < 4; rr++) {
            int r = w*4 + rr;
            int gi = i0 + r;
            if (gi >= NT) continue;
            float* srow = S + r*S_LD;
            int gvi = (gi > 0) ? (gi-1) / GRID14 : 0;
            int ghi = (gi > 0) ? (gi-1) % GRID14 : 0;

            float sv[7];
            float mx = -1e30f;
#pragma unroll
            for (int jj = 0; jj < 7; jj++) {
                int j = lane + jj*32;
                float s = -1e30f;
                if (j < NT) {
                    int tv = 0, th = 0;
                    if (gi > 0 && j > 0) {
                        tv = (j-1)/GRID14 - gvi + 15;
                        th = (j-1)%GRID14 - ghi + 15;
                    }
                    s = (srow[j] + srow[197+tv] + srow[227+th]) * 0.125f;
                }
                sv[jj] = s;
                mx = fmaxf(mx, s);
            }
#pragma unroll
            for (int o = 16; o > 0; o >>= 1) mx = fmaxf(mx, __shfl_xor_sync(0xFFFFFFFFu, mx, o));
            float sum = 0.f;
#pragma unroll
            for (int jj = 0; jj < 7; jj++) { float e = __expf(sv[jj]-mx); sv[jj] = e; sum += e; }
#pragma unroll
            for (int o = 16; o > 0; o >>= 1) sum += __shfl_xor_sync(0xFFFFFFFFu, sum, o);
            float inv = 1.f / sum;
#pragma unroll
            for (int jj = 0; jj < 7; jj++) {
                int j = lane + jj*32;
                if (j < NT) srow[j] = sv[jj]*inv;
            }
            __syncwarp();
            if (lane < TROWS) { srow[197+lane] = 0.f; srow[227+lane] = 0.f; }
            __syncwarp();
            if (gi == 0) {
                if (lane == 0) { srow[197] = 1.f; srow[227] = 1.f; }
            } else {
                if (lane < 14) {
                    float R = 0.f;
#pragma unroll
                    for (int c = 0; c < 14; c++) R += srow[1 + lane*14 + c];
                    srow[197 + (lane - gvi + 15)] = R;
                } else if (lane == 14) {
                    float p0 = srow[0];
                    srow[197] = p0; srow[227] = p0;
                } else if (lane >= 16 && lane < 30) {
                    int c = lane - 16;
                    float Cc = 0.f;
#pragma unroll
                    for (int g = 0; g < 14; g++) Cc += srow[1 + g*14 + c];
                    srow[227 + (c - ghi + 15)] = Cc;
                }
            }
            __syncwarp();
        }
        __syncthreads();

        {
            float acc0=0,acc1=0,acc2=0,acc3=0,acc4=0,acc5=0,acc6=0,acc7=0;
            const int dbase = w*8;
            const float* prow = S + lane*S_LD;
#pragma unroll 4
            for (int jp = 0; jp < JX; jp++) {
                float p = prow[jp];
                float4 v0 = *(const float4*)(vs + jp*64 + dbase);
                float4 v1 = *(const float4*)(vs + jp*64 + dbase + 4);
                acc0 += p*v0.x; acc1 += p*v0.y; acc2 += p*v0.z; acc3 += p*v0.w;
                acc4 += p*v1.x; acc5 += p*v1.y; acc6 += p*v1.z; acc7 += p*v1.w;
            }
            int gi = i0 + lane;
            if (gi < NT) {
                float* dst = g_ctx + ((size_t)(b*NT + gi))*EE + h*HD + dbase;
                *(float4*)dst     = make_float4(acc0,acc1,acc2,acc3);
                *(float4*)(dst+4) = make_float4(acc4,acc5,acc6,acc7);
            }
        }
        __syncthreads();
    }
}

// ---------------------------------------------------------------------------
extern "C" void kernel_launch(void* const* d_in, const int* in_sizes, int n_in,
                              void* d_out, int out_size)
{
    const float* x     = (const float*)d_in[0];
    const float* wq    = (const float*)d_in[1];
    const float* wk    = (const float*)d_in[2];
    const float* wv    = (const float*)d_in[3];
    const float* wproj = (const float*)d_in[4];
    const float* bproj = (const float*)d_in[5];
    const float* rk_v  = (const float*)d_in[6];
    const float* rk_h  = (const float*)d_in[7];
    const float* rv_v  = (const float*)d_in[8];
    const float* rv_h  = (const float*)d_in[9];
    float* out = (float*)d_out;

    cudaFuncSetAttribute(gemm_mma<0>, cudaFuncAttributeMaxDynamicSharedMemorySize, GEMM_SMEM);
    cudaFuncSetAttribute(gemm_mma<1>, cudaFuncAttributeMaxDynamicSharedMemorySize, GEMM_SMEM);
    cudaFuncSetAttribute(attn_k, cudaFuncAttributeMaxDynamicSharedMemorySize, ATT_SMEM_BYTES);

    dim3 g1(3*EE/128, (MT + 127)/128);
    gemm_mma<0><<<g1, 256, GEMM_SMEM>>>(x, wq, wk, wv, nullptr, nullptr);

    attn_k<<<BB*NH, 256, ATT_SMEM_BYTES>>>(rk_v, rk_h, rv_v, rv_h);

    dim3 g2(EE/128, (MT + 127)/128);
    gemm_mma<1><<<g2, 256, GEMM_SMEM>>>(nullptr, wproj, nullptr, nullptr, bproj, out);
}

// round 12
// speedup vs baseline: 2.1354x; 1.2921x over previous
#include <cuda_runtime.h>
#include <cuda_fp16.h>
#include <cstdint>

#define NH 12
#define HD 64
#define NT 197
#define BB 64
#define EE 768
#define MT (BB*NT)      // 12608
#define TROWS 30
#define GRID14 14

// scratch (static device memory; allocation-free) — identical set to round 1
__device__ __align__(16) float g_q[MT*EE];    // [(b*12+h)*197 + n]*64 + d
__device__ __align__(16) float g_k[MT*EE];
__device__ __align__(16) float g_v[MT*EE];
__device__ __align__(16) float g_ctx[MT*EE];  // [b*197+n][h*64+d]

// ===========================================================================
// helpers — value-returning asm only; no references, no struct out-params
// ===========================================================================
__device__ __forceinline__ uint32_t smem_u32(const void* p) {
    uint32_t a;
    asm("{ .reg .u64 t; cvta.to.shared.u64 t, %1; cvt.u32.u64 %0, t; }" : "=r"(a) : "l"(p));
    return a;
}
// pack two f32 into f16x2 word: lo at low half, hi at high half
__device__ __forceinline__ uint32_t f2h2(float lo, float hi_) {
    uint32_t r;
    asm("cvt.rn.f16x2.f32 %0, %1, %2;" : "=r"(r) : "f"(hi_), "f"(lo));
    return r;
}
// round f32 through f16 and back (for residual computation)
__device__ __forceinline__ float rn16(float x) {
    float r;
    asm("{ .reg .f16 t; cvt.rn.f16.f32 t, %1; cvt.f32.f16 %0, t; }" : "=f"(r) : "f"(x));
    return r;
}
// store f32 as f16 to a byte pointer (value semantics only)
__device__ __forceinline__ void sth(char* p, float v) {
    unsigned short u;
    asm("{ .reg .f16 t; cvt.rn.f16.f32 t, %1; mov.b16 %0, t; }" : "=h"(u) : "f"(v));
    *(unsigned short*)p = u;
}
#define LDSM4(r0,r1,r2,r3,addr) \
    asm volatile("ldmatrix.sync.aligned.m8n8.x4.shared.b16 {%0,%1,%2,%3}, [%4];" \
                 : "=r"(r0), "=r"(r1), "=r"(r2), "=r"(r3) : "r"(addr))
#define LDSM4T(r0,r1,r2,r3,addr) \
    asm volatile("ldmatrix.sync.aligned.m8n8.x4.trans.shared.b16 {%0,%1,%2,%3}, [%4];" \
                 : "=r"(r0), "=r"(r1), "=r"(r2), "=r"(r3) : "r"(addr))
#define MMA_S(d0,d1,d2,d3, a0,a1,a2,a3, b0,b1) \
    asm volatile("mma.sync.aligned.m16n8k16.row.col.f32.f16.f16.f32 " \
                 "{%0,%1,%2,%3}, {%4,%5,%6,%7}, {%8,%9}, {%0,%1,%2,%3};" \
                 : "+f"(d0), "+f"(d1), "+f"(d2), "+f"(d3) \
                 : "r"(a0), "r"(a1), "r"(a2), "r"(a3), "r"(b0), "r"(b1))

// ===========================================================================
// mma.sync fp16 3-product GEMM (unchanged from round 9 — verified)
// ===========================================================================
#define A_STRIDE 40
#define B_STRIDE 136
#define OFF_AL 10240
#define OFF_BH 20480
#define OFF_BL 29184
#define GEMM_STG 37888
#define GEMM_SMEM (2*GEMM_STG)

#define DECL_ACC(m,n) \
    float c##m##n##_0 = 0.f, c##m##n##_1 = 0.f, c##m##n##_2 = 0.f, c##m##n##_3 = 0.f

#define MMA3(m,n, B0,B1, C0,C1) \
    MMA_S(c##m##n##_0,c##m##n##_1,c##m##n##_2,c##m##n##_3, \
          ah##m##_0,ah##m##_1,ah##m##_2,ah##m##_3, B0,B1); \
    MMA_S(c##m##n##_0,c##m##n##_1,c##m##n##_2,c##m##n##_3, \
          ah##m##_0,ah##m##_1,ah##m##_2,ah##m##_3, C0,C1); \
    MMA_S(c##m##n##_0,c##m##n##_1,c##m##n##_2,c##m##n##_3, \
          al##m##_0,al##m##_1,al##m##_2,al##m##_3, B0,B1)

#define LDA(m, addr_) \
    LDSM4(ah##m##_0,ah##m##_1,ah##m##_2,ah##m##_3, (addr_)); \
    LDSM4(al##m##_0,al##m##_1,al##m##_2,al##m##_3, (addr_) + OFF_AL)

#define KSTEP(ks_) do { \
    uint32_t ah0_0,ah0_1,ah0_2,ah0_3, ah1_0,ah1_1,ah1_2,ah1_3; \
    uint32_t ah2_0,ah2_1,ah2_2,ah2_3, ah3_0,ah3_1,ah3_2,ah3_3; \
    uint32_t al0_0,al0_1,al0_2,al0_3, al1_0,al1_1,al1_2,al1_3; \
    uint32_t al2_0,al2_1,al2_2,al2_3, al3_0,al3_1,al3_2,al3_3; \
    uint32_t bh0_0,bh0_1,bh0_2,bh0_3, bh1_0,bh1_1,bh1_2,bh1_3; \
    uint32_t bl0_0,bl0_1,bl0_2,bl0_3, bl1_0,bl1_1,bl1_2,bl1_3; \
    uint32_t a0_ = stg + (uint32_t)((wm0 + r15) * A_STRIDE + (ks_)*16 + h16*8) * 2; \
    LDA(0, a0_); \
    LDA(1, a0_ + (uint32_t)(16 * A_STRIDE * 2)); \
    LDA(2, a0_ + (uint32_t)(32 * A_STRIDE * 2)); \
    LDA(3, a0_ + (uint32_t)(48 * A_STRIDE * 2)); \
    uint32_t b0_ = stg + OFF_BH + (uint32_t)(((ks_)*16 + r15) * B_STRIDE + wn0 + h16*8) * 2; \
    uint32_t b1_ = b0_ + 32; \
    LDSM4T(bh0_0,bh0_1,bh0_2,bh0_3, b0_); \
    LDSM4T(bh1_0,bh1_1,bh1_2,bh1_3, b1_); \
    LDSM4T(bl0_0,bl0_1,bl0_2,bl0_3, b0_ + (OFF_BL - OFF_BH)); \
    LDSM4T(bl1_0,bl1_1,bl1_2,bl1_3, b1_ + (OFF_BL - OFF_BH)); \
    MMA3(0,0, bh0_0,bh0_1, bl0_0,bl0_1); \
    MMA3(0,1, bh0_2,bh0_3, bl0_2,bl0_3); \
    MMA3(0,2, bh1_0,bh1_1, bl1_0,bl1_1); \
    MMA3(0,3, bh1_2,bh1_3, bl1_2,bl1_3); \
    MMA3(1,0, bh0_0,bh0_1, bl0_0,bl0_1); \
    MMA3(1,1, bh0_2,bh0_3, bl0_2,bl0_3); \
    MMA3(1,2, bh1_0,bh1_1, bl1_0,bl1_1); \
    MMA3(1,3, bh1_2,bh1_3, bl1_2,bl1_3); \
    MMA3(2,0, bh0_0,bh0_1, bl0_0,bl0_1); \
    MMA3(2,1, bh0_2,bh0_3, bl0_2,bl0_3); \
    MMA3(2,2, bh1_0,bh1_1, bl1_0,bl1_1); \
    MMA3(2,3, bh1_2,bh1_3, bl1_2,bl1_3); \
    MMA3(3,0, bh0_0,bh0_1, bl0_0,bl0_1); \
    MMA3(3,1, bh0_2,bh0_3, bl0_2,bl0_3); \
    MMA3(3,2, bh1_0,bh1_1, bl1_0,bl1_1); \
    MMA3(3,3, bh1_2,bh1_3, bl1_2,bl1_3); \
} while(0)

#define LDA4(dst, i_, k0_) do { \
    int row_ = (i_) >> 3, c4_ = (i_) & 7; int gm_ = m0 + row_; \
    dst = (gm_ < MT) ? *(const float4*)(Ap + (size_t)gm_ * EE + (k0_) + c4_ * 4) \
                     : make_float4(0.f, 0.f, 0.f, 0.f); \
} while(0)
#define LDB4(dst, i_, k0_) do { \
    int kr_ = (i_) >> 5, c4_ = (i_) & 31; \
    dst = *(const float4*)(Bp + (size_t)((k0_) + kr_) * EE + bcol0 + c4_ * 4); \
} while(0)
#define LDG_CHUNK(k0_) do { \
    LDA4(fa0, tid,       (k0_)); LDA4(fa1, tid + 256, (k0_)); \
    LDA4(fa2, tid + 512, (k0_)); LDA4(fa3, tid + 768, (k0_)); \
    LDB4(fb0, tid,       (k0_)); LDB4(fb1, tid + 256, (k0_)); \
    LDB4(fb2, tid + 512, (k0_)); LDB4(fb3, tid + 768, (k0_)); \
} while(0)

#define STS_A1(fv, i_) do { \
    int row_ = (i_) >> 3, c4_ = (i_) & 7; \
    uint32_t h01_ = f2h2(fv.x, fv.y), h23_ = f2h2(fv.z, fv.w); \
    uint32_t l01_ = f2h2(fv.x - rn16(fv.x), fv.y - rn16(fv.y)); \
    uint32_t l23_ = f2h2(fv.z - rn16(fv.z), fv.w - rn16(fv.w)); \
    char* p_ = stgp + row_ * (A_STRIDE * 2) + c4_ * 8; \
    *(uint2*)p_ = make_uint2(h01_, h23_); \
    *(uint2*)(p_ + OFF_AL) = make_uint2(l01_, l23_); \
} while(0)
#define STS_B1(fv, i_) do { \
    int kr_ = (i_) >> 5, c4_ = (i_) & 31; \
    uint32_t h01_ = f2h2(fv.x, fv.y), h23_ = f2h2(fv.z, fv.w); \
    uint32_t l01_ = f2h2(fv.x - rn16(fv.x), fv.y - rn16(fv.y)); \
    uint32_t l23_ = f2h2(fv.z - rn16(fv.z), fv.w - rn16(fv.w)); \
    char* p_ = stgp + OFF_BH + kr_ * (B_STRIDE * 2) + c4_ * 8; \
    *(uint2*)p_ = make_uint2(h01_, h23_); \
    *(uint2*)(p_ + (OFF_BL - OFF_BH)) = make_uint2(l01_, l23_); \
} while(0)

#define STORE2(r_, col_, v0, v1) do { \
    if (MODE == 1) { \
        float2 o_; o_.x = (v0) + bias[(col_)]; o_.y = (v1) + bias[(col_)+1]; \
        *(float2*)(Cout + (size_t)(r_) * EE + (col_)) = o_; \
    } else { \
        int bb_ = (r_) / NT, nn_ = (r_) - bb_ * NT; \
        int which_ = (col_) / EE, cc_ = (col_) - which_ * EE; \
        int hh_ = cc_ >> 6, dd_ = cc_ & 63; \
        float* bp_ = (which_ == 0) ? g_q : (which_ == 1) ? g_k : g_v; \
        *(float2*)(bp_ + (((size_t)(bb_ * NH + hh_)) * NT + nn_) * HD + dd_) = \
            make_float2((v0), (v1)); \
    } \
} while(0)

#define STORE_TILE(m,n) do { \
    int r_ = m0 + wm0 + (m)*16 + (lane >> 2); \
    int cb_ = n0 + wn0 + (n)*8 + (lane & 3) * 2; \
    if (r_ < MT)     STORE2(r_,     cb_, c##m##n##_0, c##m##n##_1); \
    if (r_ + 8 < MT) STORE2(r_ + 8, cb_, c##m##n##_2, c##m##n##_3); \
} while(0)

template<int MODE>
__global__ __launch_bounds__(256, 1)
void gemm_mma(const float* __restrict__ A,
              const float* __restrict__ B0, const float* __restrict__ B1,
              const float* __restrict__ B2, const float* __restrict__ bias,
              float* __restrict__ Cout)
{
    extern __shared__ char smem_raw[];
    const uint32_t sb = smem_u32(smem_raw);
    const int tid = threadIdx.x;
    const int lane = tid & 31, wid = tid >> 5;
    const int m0 = blockIdx.y * 128, n0 = blockIdx.x * 128;
    const int wm0 = (wid >> 2) * 64, wn0 = (wid & 3) * 32;
    const int r15 = lane & 15, h16 = lane >> 4;

    const float* Ap = (MODE == 0) ? A : g_ctx;
    const float* Bp;
    int bcol0;
    if (MODE == 0) {
        int which = n0 / EE;
        Bp = (which == 0) ? B0 : (which == 1) ? B1 : B2;
        bcol0 = n0 - which * EE;
    } else { Bp = B0; bcol0 = n0; }

    DECL_ACC(0,0); DECL_ACC(0,1); DECL_ACC(0,2); DECL_ACC(0,3);
    DECL_ACC(1,0); DECL_ACC(1,1); DECL_ACC(1,2); DECL_ACC(1,3);
    DECL_ACC(2,0); DECL_ACC(2,1); DECL_ACC(2,2); DECL_ACC(2,3);
    DECL_ACC(3,0); DECL_ACC(3,1); DECL_ACC(3,2); DECL_ACC(3,3);

    float4 fa0, fa1, fa2, fa3, fb0, fb1, fb2, fb3;
    LDG_CHUNK(0);

    const int NC = 24;
#pragma unroll 1
    for (int c = 0; c < NC; c++) {
        {
            char* stgp = smem_raw + (c & 1) * GEMM_STG;
            STS_A1(fa0, tid);       STS_A1(fa1, tid + 256);
            STS_A1(fa2, tid + 512); STS_A1(fa3, tid + 768);
            STS_B1(fb0, tid);       STS_B1(fb1, tid + 256);
            STS_B1(fb2, tid + 512); STS_B1(fb3, tid + 768);
        }
        __syncthreads();
        if (c + 1 < NC) LDG_CHUNK((c + 1) * 32);
        const uint32_t stg = sb + (c & 1) * GEMM_STG;
        KSTEP(0);
        KSTEP(1);
        __syncthreads();
    }

    STORE_TILE(0,0); STORE_TILE(0,1); STORE_TILE(0,2); STORE_TILE(0,3);
    STORE_TILE(1,0); STORE_TILE(1,1); STORE_TILE(1,2); STORE_TILE(1,3);
    STORE_TILE(2,0); STORE_TILE(2,1); STORE_TILE(2,2); STORE_TILE(2,3);
    STORE_TILE(3,0); STORE_TILE(3,1); STORE_TILE(3,2); STORE_TILE(3,3);
}

// ===========================================================================
// Fused attention with mma.sync GEMMs.
// One CTA per (b,h), 256 threads (8 warps). Extended-J trick:
//   score cols: 0..196 = K, 197..226 = rk_v, 227..256 = rk_h (257, pad 272)
//   PV rows:    0..196 = V, 197..226 = rv_v, 227..256 = rv_h (pad rows zeroed)
// smem: K^T hi/lo [64][272]h, V hi/lo [272][72]h, Q hi/lo [32][72]h,
//       P hi/lo [32][272]h, S fp32 [32][272].
// ===========================================================================
#define SKLD 272
#define SVLD 72
#define SQLD 72
#define SPLD 272
#define SSLD 272
#define AO_KSH 0
#define AO_KSL 34816
#define AO_VSH 69632
#define AO_VSL 108800
#define AO_QSH 147968
#define AO_QSL 152576
#define AO_PH  157184
#define AO_PL  174592
#define AO_S   192000
#define ATT_SMEM_BYTES 226816

#define LOADQ(ks) \
    LDSM4(qh##ks##_0,qh##ks##_1,qh##ks##_2,qh##ks##_3, qa_ + (ks)*32); \
    LDSM4(ql##ks##_0,ql##ks##_1,ql##ks##_2,ql##ks##_3, qa_ + (ks)*32 + (AO_QSL - AO_QSH))

#define SCORE_K(ks) do { \
    uint32_t kh0,kh1,kh2,kh3, kl0,kl1,kl2,kl3; \
    uint32_t ka_ = sb + AO_KSH + (uint32_t)(((ks)*16 + r15) * SKLD + n0 + h16*8) * 2; \
    LDSM4T(kh0,kh1,kh2,kh3, ka_); \
    LDSM4T(kl0,kl1,kl2,kl3, ka_ + (AO_KSL - AO_KSH)); \
    MMA_S(e0,e1,e2,e3, qh##ks##_0,qh##ks##_1,qh##ks##_2,qh##ks##_3, kh0,kh1); \
    MMA_S(e0,e1,e2,e3, qh##ks##_0,qh##ks##_1,qh##ks##_2,qh##ks##_3, kl0,kl1); \
    MMA_S(e0,e1,e2,e3, ql##ks##_0,ql##ks##_1,ql##ks##_2,ql##ks##_3, kh0,kh1); \
    MMA_S(f0,f1,f2,f3, qh##ks##_0,qh##ks##_1,qh##ks##_2,qh##ks##_3, kh2,kh3); \
    MMA_S(f0,f1,f2,f3, qh##ks##_0,qh##ks##_1,qh##ks##_2,qh##ks##_3, kl2,kl3); \
    MMA_S(f0,f1,f2,f3, ql##ks##_0,ql##ks##_1,ql##ks##_2,ql##ks##_3, kh2,kh3); \
} while(0)

__global__ __launch_bounds__(256, 1)
void attn_k(const float* __restrict__ rk_v, const float* __restrict__ rk_h,
            const float* __restrict__ rv_v, const float* __restrict__ rv_h)
{
    extern __shared__ char smem_raw[];
    char* smr = smem_raw;
    const uint32_t sb = smem_u32(smem_raw);
    const int bh = blockIdx.x;
    const int tid = threadIdx.x;
    const int w = tid >> 5, lane = tid & 31;
    const int r15 = lane & 15, h16 = lane >> 4;
    const int b = bh / NH, h = bh - b*NH;
    const float* Kb = g_k + (size_t)bh * NT * HD;
    const float* Vb = g_v + (size_t)bh * NT * HD;
    const float* Qb = g_q + (size_t)bh * NT * HD;

    // ---- fill K^T hi/lo (rows d, cols j) + rk tables ----
    for (int i = tid; i < NT*HD; i += 256) {
        int j = i >> 6, d = i & 63;
        float v = Kb[i], hv = rn16(v);
        size_t o = (size_t)(d*SKLD + j) * 2;
        sth(smr + AO_KSH + o, v);
        sth(smr + AO_KSL + o, v - hv);
    }
    for (int i = tid; i < TROWS*HD; i += 256) {
        int t = i >> 6, d = i & 63;
        float v = rk_v[i], hv = rn16(v);
        size_t o = (size_t)(d*SKLD + 197 + t) * 2;
        sth(smr + AO_KSH + o, v); sth(smr + AO_KSL + o, v - hv);
        float v2 = rk_h[i], hv2 = rn16(v2);
        size_t o2 = (size_t)(d*SKLD + 227 + t) * 2;
        sth(smr + AO_KSH + o2, v2); sth(smr + AO_KSL + o2, v2 - hv2);
    }
    // Zero V pad rows (REQUIRED: PV reads rows 257..271):
    for (int i = tid; i < (15*SVLD*2)/4; i += 256) {
        *(uint32_t*)(smr + AO_VSH + 257*SVLD*2 + i*4) = 0;
        *(uint32_t*)(smr + AO_VSL + 257*SVLD*2 + i*4) = 0;
    }
    // ---- fill V hi/lo (rows j, cols d) + rv tables ----
    for (int i = tid; i < NT*HD; i += 256) {
        int j = i >> 6, d = i & 63;
        float v = Vb[i], hv = rn16(v);
        size_t o = (size_t)(j*SVLD + d) * 2;
        sth(smr + AO_VSH + o, v);
        sth(smr + AO_VSL + o, v - hv);
    }
    for (int i = tid; i < TROWS*HD; i += 256) {
        int t = i >> 6, d = i & 63;
        float v = rv_v[i], hv = rn16(v);
        size_t o = (size_t)((197 + t)*SVLD + d) * 2;
        sth(smr + AO_VSH + o, v); sth(smr + AO_VSL + o, v - hv);
        float v2 = rv_h[i], hv2 = rn16(v2);
        size_t o2 = (size_t)((227 + t)*SVLD + d) * 2;
        sth(smr + AO_VSH + o2, v2); sth(smr + AO_VSL + o2, v2 - hv2);
    }
    __syncthreads();

    for (int i0 = 0; i0 < NT; i0 += 32) {
        // ---- Q block hi/lo ----
        for (int i = tid; i < 32*HD; i += 256) {
            int r = i >> 6, d = i & 63;
            int gi = i0 + r;
            float v = (gi < NT) ? Qb[gi*HD + d] : 0.f;
            float hv = rn16(v);
            size_t o = (size_t)(r*SQLD + d) * 2;
            sth(smr + AO_QSH + o, v);
            sth(smr + AO_QSL + o, v - hv);
        }
        __syncthreads();

        // ---- score GEMM: S[32][272] = Q @ K_ext^T (hi/lo 3-product) ----
        {
            const int am0 = (w & 1) * 16;
            uint32_t qa_ = sb + AO_QSH + (uint32_t)((am0 + r15) * SQLD + h16*8) * 2;
            uint32_t qh0_0,qh0_1,qh0_2,qh0_3, qh1_0,qh1_1,qh1_2,qh1_3;
            uint32_t qh2_0,qh2_1,qh2_2,qh2_3, qh3_0,qh3_1,qh3_2,qh3_3;
            uint32_t ql0_0,ql0_1,ql0_2,ql0_3, ql1_0,ql1_1,ql1_2,ql1_3;
            uint32_t ql2_0,ql2_1,ql2_2,ql2_3, ql3_0,ql3_1,ql3_2,ql3_3;
            LOADQ(0); LOADQ(1); LOADQ(2); LOADQ(3);
            float* S = (float*)(smr + AO_S);
#pragma unroll 1
            for (int p = (w >> 1); p < 17; p += 4) {
                int n0 = p * 16;
                float e0=0,e1=0,e2=0,e3=0, f0=0,f1=0,f2=0,f3=0;
                SCORE_K(0); SCORE_K(1); SCORE_K(2); SCORE_K(3);
                float* sr0 = S + (am0 + (lane >> 2)) * SSLD + n0 + (lane & 3) * 2;
                *(float2*)sr0 = make_float2(e0, e1);
                *(float2*)(sr0 + 8*SSLD) = make_float2(e2, e3);
                *(float2*)(sr0 + 8) = make_float2(f0, f1);
                *(float2*)(sr0 + 8*SSLD + 8) = make_float2(f2, f3);
            }
        }
        __syncthreads();

        // ---- softmax + rel-pos bins (warp w: rows w*4..w*4+3) ----
        {
            float* S = (float*)(smr + AO_S);
            for (int rr = 0; rr < 4; rr++) {
                int r = w*4 + rr;
                int gi = i0 + r;
                if (gi >= NT) continue;
                float* srow = S + r*SSLD;
                int gvi = (gi > 0) ? (gi-1) / GRID14 : 0;
                int ghi = (gi > 0) ? (gi-1) % GRID14 : 0;

                float sv[7];
                float mx = -1e30f;
#pragma unroll
                for (int jj = 0; jj < 7; jj++) {
                    int j = lane + jj*32;
                    float s = -1e30f;
                    if (j < NT) {
                        int tv = 0, th = 0;
                        if (gi > 0 && j > 0) {
                            tv = (j-1)/GRID14 - gvi + 15;
                            th = (j-1)%GRID14 - ghi + 15;
                        }
                        s = (srow[j] + srow[197+tv] + srow[227+th]) * 0.125f;
                    }
                    sv[jj] = s;
                    mx = fmaxf(mx, s);
                }
#pragma unroll
                for (int o = 16; o > 0; o >>= 1) mx = fmaxf(mx, __shfl_xor_sync(0xFFFFFFFFu, mx, o));
                float sum = 0.f;
#pragma unroll
                for (int jj = 0; jj < 7; jj++) { float e = __expf(sv[jj]-mx); sv[jj] = e; sum += e; }
#pragma unroll
                for (int o = 16; o > 0; o >>= 1) sum += __shfl_xor_sync(0xFFFFFFFFu, sum, o);
                float inv = 1.f / sum;
#pragma unroll
                for (int jj = 0; jj < 7; jj++) {
                    int j = lane + jj*32;
                    if (j < NT) srow[j] = sv[jj]*inv;
                }
                __syncwarp();
                if (lane < TROWS) { srow[197+lane] = 0.f; srow[227+lane] = 0.f; }
                __syncwarp();
                if (gi == 0) {
                    if (lane == 0) { srow[197] = 1.f; srow[227] = 1.f; }
                } else {
                    if (lane < 14) {
                        float R = 0.f;
#pragma unroll
                        for (int c = 0; c < 14; c++) R += srow[1 + lane*14 + c];
                        srow[197 + (lane - gvi + 15)] = R;
                    } else if (lane == 14) {
                        float p0 = srow[0];
                        srow[197] = p0; srow[227] = p0;
                    } else if (lane >= 16 && lane < 30) {
                        int c = lane - 16;
                        float Cc = 0.f;
#pragma unroll
                        for (int g = 0; g < 14; g++) Cc += srow[1 + g*14 + c];
                        srow[227 + (c - ghi + 15)] = Cc;
                    }
                }
                __syncwarp();
            }
        }
        __syncthreads();

        // ---- convert P (S rows, cols 0..256; pad 257..271 = 0) to hi/lo ----
        {
            float* S = (float*)(smr + AO_S);
            for (int idx = tid; idx < 32 * SPLD; idx += 256) {
                int row = idx / SPLD, col = idx - row * SPLD;
                float v = (col < 257) ? S[row * SSLD + col] : 0.f;
                float hv = rn16(v);
                sth(smr + AO_PH + (size_t)idx * 2, v);
                sth(smr + AO_PL + (size_t)idx * 2, v - hv);
            }
        }
        __syncthreads();

        // ---- PV GEMM: out[32][64] = P @ V_ext (hi/lo 3-product) ----
        {
            const int am0 = (w & 1) * 16;
            const int n0v = (w >> 1) * 16;
            float u0=0,u1=0,u2=0,u3=0, t0=0,t1=0,t2=0,t3=0;
#pragma unroll 1
            for (int ks = 0; ks < 17; ks++) {
                uint32_t pa0,pa1,pa2,pa3, pb0,pb1,pb2,pb3;
                uint32_t vh0,vh1,vh2,vh3, vl0,vl1,vl2,vl3;
                uint32_t pa_ = sb + AO_PH + (uint32_t)((am0 + r15) * SPLD + ks*16 + h16*8) * 2;
                LDSM4(pa0,pa1,pa2,pa3, pa_);
                LDSM4(pb0,pb1,pb2,pb3, pa_ + (AO_PL - AO_PH));
                uint32_t va_ = sb + AO_VSH + (uint32_t)((ks*16 + r15) * SVLD + n0v + h16*8) * 2;
                LDSM4T(vh0,vh1,vh2,vh3, va_);
                LDSM4T(vl0,vl1,vl2,vl3, va_ + (AO_VSL - AO_VSH));
                MMA_S(u0,u1,u2,u3, pa0,pa1,pa2,pa3, vh0,vh1);
                MMA_S(u0,u1,u2,u3, pa0,pa1,pa2,pa3, vl0,vl1);
                MMA_S(u0,u1,u2,u3, pb0,pb1,pb2,pb3, vh0,vh1);
                MMA_S(t0,t1,t2,t3, pa0,pa1,pa2,pa3, vh2,vh3);
                MMA_S(t0,t1,t2,t3, pa0,pa1,pa2,pa3, vl2,vl3);
                MMA_S(t0,t1,t2,t3, pb0,pb1,pb2,pb3, vh2,vh3);
            }
            int gi0 = i0 + am0 + (lane >> 2);
            int cc = n0v + (lane & 3) * 2;
            if (gi0 < NT) {
                float* dst = g_ctx + ((size_t)(b*NT + gi0))*EE + h*HD;
                *(float2*)(dst + cc) = make_float2(u0, u1);
                *(float2*)(dst + cc + 8) = make_float2(t0, t1);
            }
            if (gi0 + 8 < NT) {
                float* dst = g_ctx + ((size_t)(b*NT + gi0 + 8))*EE + h*HD;
                *(float2*)(dst + cc) = make_float2(u2, u3);
                *(float2*)(dst + cc + 8) = make_float2(t2, t3);
            }
        }
        __syncthreads();
    }
}

// ---------------------------------------------------------------------------
extern "C" void kernel_launch(void* const* d_in, const int* in_sizes, int n_in,
                              void* d_out, int out_size)
{
    const float* x     = (const float*)d_in[0];
    const float* wq    = (const float*)d_in[1];
    const float* wk    = (const float*)d_in[2];
    const float* wv    = (const float*)d_in[3];
    const float* wproj = (const float*)d_in[4];
    const float* bproj = (const float*)d_in[5];
    const float* rk_v  = (const float*)d_in[6];
    const float* rk_h  = (const float*)d_in[7];
    const float* rv_v  = (const float*)d_in[8];
    const float* rv_h  = (const float*)d_in[9];
    float* out = (float*)d_out;

    cudaFuncSetAttribute(gemm_mma<0>, cudaFuncAttributeMaxDynamicSharedMemorySize, GEMM_SMEM);
    cudaFuncSetAttribute(gemm_mma<1>, cudaFuncAttributeMaxDynamicSharedMemorySize, GEMM_SMEM);
    cudaFuncSetAttribute(attn_k, cudaFuncAttributeMaxDynamicSharedMemorySize, ATT_SMEM_BYTES);

    dim3 g1(3*EE/128, (MT + 127)/128);
    gemm_mma<0><<<g1, 256, GEMM_SMEM>>>(x, wq, wk, wv, nullptr, nullptr);

    attn_k<<<BB*NH, 256, ATT_SMEM_BYTES>>>(rk_v, rk_h, rv_v, rv_h);

    dim3 g2(EE/128, (MT + 127)/128);
    gemm_mma<1><<<g2, 256, GEMM_SMEM>>>(nullptr, wproj, nullptr, nullptr, bproj, out);
}

// round 16
// speedup vs baseline: 2.1507x; 1.0072x over previous
#include <cuda_runtime.h>
#include <cuda_fp16.h>
#include <cstdint>

#define NH 12
#define HD 64
#define NT 197
#define BB 64
#define EE 768
#define MT (BB*NT)      // 12608
#define NBH (BB*NH)     // 768
#define TROWS 30
#define GRID14 14
#define NTP 208         // padded NT for K^T global

// scratch (static device memory; allocation-free). Referenced ONLY from device
// code — never passed as kernel arguments from host (that was the 2^27 bug).
__device__ __align__(16) __half g_xh[MT*EE];
__device__ __align__(16) __half g_xl[MT*EE];
__device__ __align__(16) __half g_wh[EE*3*EE];   // [k][2304] = wq|wk|wv
__device__ __align__(16) __half g_wl[EE*3*EE];
__device__ __align__(16) __half g_ph[EE*EE];     // wproj [k][768]
__device__ __align__(16) __half g_pl[EE*EE];
__device__ __align__(16) __half g_qh[NBH*NT*HD]; // [bh][n][d]
__device__ __align__(16) __half g_ql[NBH*NT*HD];
__device__ __align__(16) __half g_vh[NBH*NT*HD];
__device__ __align__(16) __half g_vl[NBH*NT*HD];
__device__ __align__(16) __half g_kth[NBH*HD*NTP]; // [bh][d][208] transposed K
__device__ __align__(16) __half g_ktl[NBH*HD*NTP];
__device__ __align__(16) __half g_ch[MT*EE];     // ctx [row][768]
__device__ __align__(16) __half g_cl[MT*EE];

// ===========================================================================
// helpers — value-returning asm only
// ===========================================================================
__device__ __forceinline__ uint32_t smem_u32(const void* p) {
    uint32_t a;
    asm("{ .reg .u64 t; cvta.to.shared.u64 t, %1; cvt.u32.u64 %0, t; }" : "=r"(a) : "l"(p));
    return a;
}
__device__ __forceinline__ uint32_t f2h2(float lo, float hi_) {
    uint32_t r;
    asm("cvt.rn.f16x2.f32 %0, %1, %2;" : "=r"(r) : "f"(hi_), "f"(lo));
    return r;
}
__device__ __forceinline__ float rn16(float x) {
    float r;
    asm("{ .reg .f16 t; cvt.rn.f16.f32 t, %1; cvt.f32.f16 %0, t; }" : "=f"(r) : "f"(x));
    return r;
}
__device__ __forceinline__ void sth(char* p, float v) {
    unsigned short u;
    asm("{ .reg .f16 t; cvt.rn.f16.f32 t, %1; mov.b16 %0, t; }" : "=h"(u) : "f"(v));
    *(unsigned short*)p = u;
}
#define LDSM4(r0,r1,r2,r3,addr) \
    asm volatile("ldmatrix.sync.aligned.m8n8.x4.shared.b16 {%0,%1,%2,%3}, [%4];" \
                 : "=r"(r0), "=r"(r1), "=r"(r2), "=r"(r3) : "r"(addr))
#define LDSM4T(r0,r1,r2,r3,addr) \
    asm volatile("ldmatrix.sync.aligned.m8n8.x4.trans.shared.b16 {%0,%1,%2,%3}, [%4];" \
                 : "=r"(r0), "=r"(r1), "=r"(r2), "=r"(r3) : "r"(addr))
#define MMA_S(d0,d1,d2,d3, a0,a1,a2,a3, b0,b1) \
    asm volatile("mma.sync.aligned.m16n8k16.row.col.f32.f16.f16.f32 " \
                 "{%0,%1,%2,%3}, {%4,%5,%6,%7}, {%8,%9}, {%0,%1,%2,%3};" \
                 : "+f"(d0), "+f"(d1), "+f"(d2), "+f"(d3) \
                 : "r"(a0), "r"(a1), "r"(a2), "r"(a3), "r"(b0), "r"(b1))

// ===========================================================================
// prepass: fp32 -> fp16 hi/lo splits (write device globals from device code)
// ===========================================================================
#define SPLIT4(v, hdst, ldst) do { \
    uint32_t h0_ = f2h2((v).x, (v).y), h1_ = f2h2((v).z, (v).w); \
    uint32_t l0_ = f2h2((v).x - rn16((v).x), (v).y - rn16((v).y)); \
    uint32_t l1_ = f2h2((v).z - rn16((v).z), (v).w - rn16((v).w)); \
    *(uint2*)(hdst) = make_uint2(h0_, h1_); \
    *(uint2*)(ldst) = make_uint2(l0_, l1_); \
} while(0)

__global__ void split_x_k(const float* __restrict__ x) {
    size_t i = (size_t)blockIdx.x * 256 + threadIdx.x;
    if (i >= (size_t)MT * EE / 4) return;
    float4 v = *(const float4*)(x + i * 4);
    SPLIT4(v, &g_xh[i*4], &g_xl[i*4]);
}
__global__ void split_wqkv_k(const float* __restrict__ wq, const float* __restrict__ wk,
                             const float* __restrict__ wv) {
    size_t i = (size_t)blockIdx.x * 256 + threadIdx.x;
    if (i >= (size_t)EE * 576) return;
    int k = (int)(i / 576), c4 = (int)(i % 576) * 4;
    const float* src = (c4 < 768) ? (wq + (size_t)k * 768 + c4)
                     : (c4 < 1536) ? (wk + (size_t)k * 768 + c4 - 768)
                                   : (wv + (size_t)k * 768 + c4 - 1536);
    float4 v = *(const float4*)src;
    SPLIT4(v, &g_wh[(size_t)k*2304 + c4], &g_wl[(size_t)k*2304 + c4]);
}
__global__ void split_wp_k(const float* __restrict__ wp) {
    size_t i = (size_t)blockIdx.x * 256 + threadIdx.x;
    if (i >= (size_t)EE * EE / 4) return;
    float4 v = *(const float4*)(wp + i * 4);
    SPLIT4(v, &g_ph[i*4], &g_pl[i*4]);
}

// ===========================================================================
// mma.sync fp16 3-product GEMM, fp16 pre-split inputs selected INTERNALLY
// by MODE (no device symbols in launch args).
// MODE 0: A=g_xh/l [MT][768], B=g_wh/l [768][2304]; epilogue scatters
//         q (natural), v (natural), k (transposed) as fp16 hi/lo.
// MODE 1: A=g_ch/l, B=g_ph/l [768][768]; epilogue fp32 out + bias.
// ===========================================================================
#define A_STRIDE 40
#define B_STRIDE 136
#define OFF_AL 10240
#define OFF_BH 20480
#define OFF_BL 29184
#define GEMM_STG 37888
#define GEMM_SMEM (2*GEMM_STG)

#define DECL_ACC(m,n) \
    float c##m##n##_0 = 0.f, c##m##n##_1 = 0.f, c##m##n##_2 = 0.f, c##m##n##_3 = 0.f

#define MMA3(m,n, B0,B1, C0,C1) \
    MMA_S(c##m##n##_0,c##m##n##_1,c##m##n##_2,c##m##n##_3, \
          ah##m##_0,ah##m##_1,ah##m##_2,ah##m##_3, B0,B1); \
    MMA_S(c##m##n##_0,c##m##n##_1,c##m##n##_2,c##m##n##_3, \
          ah##m##_0,ah##m##_1,ah##m##_2,ah##m##_3, C0,C1); \
    MMA_S(c##m##n##_0,c##m##n##_1,c##m##n##_2,c##m##n##_3, \
          al##m##_0,al##m##_1,al##m##_2,al##m##_3, B0,B1)

#define LDA(m, addr_) \
    LDSM4(ah##m##_0,ah##m##_1,ah##m##_2,ah##m##_3, (addr_)); \
    LDSM4(al##m##_0,al##m##_1,al##m##_2,al##m##_3, (addr_) + OFF_AL)

#define KSTEP(ks_) do { \
    uint32_t ah0_0,ah0_1,ah0_2,ah0_3, ah1_0,ah1_1,ah1_2,ah1_3; \
    uint32_t ah2_0,ah2_1,ah2_2,ah2_3, ah3_0,ah3_1,ah3_2,ah3_3; \
    uint32_t al0_0,al0_1,al0_2,al0_3, al1_0,al1_1,al1_2,al1_3; \
    uint32_t al2_0,al2_1,al2_2,al2_3, al3_0,al3_1,al3_2,al3_3; \
    uint32_t bh0_0,bh0_1,bh0_2,bh0_3, bh1_0,bh1_1,bh1_2,bh1_3; \
    uint32_t bl0_0,bl0_1,bl0_2,bl0_3, bl1_0,bl1_1,bl1_2,bl1_3; \
    uint32_t a0_ = stg + (uint32_t)((wm0 + r15) * A_STRIDE + (ks_)*16 + h16*8) * 2; \
    LDA(0, a0_); \
    LDA(1, a0_ + (uint32_t)(16 * A_STRIDE * 2)); \
    LDA(2, a0_ + (uint32_t)(32 * A_STRIDE * 2)); \
    LDA(3, a0_ + (uint32_t)(48 * A_STRIDE * 2)); \
    uint32_t b0_ = stg + OFF_BH + (uint32_t)(((ks_)*16 + r15) * B_STRIDE + wn0 + h16*8) * 2; \
    uint32_t b1_ = b0_ + 32; \
    LDSM4T(bh0_0,bh0_1,bh0_2,bh0_3, b0_); \
    LDSM4T(bh1_0,bh1_1,bh1_2,bh1_3, b1_); \
    LDSM4T(bl0_0,bl0_1,bl0_2,bl0_3, b0_ + (OFF_BL - OFF_BH)); \
    LDSM4T(bl1_0,bl1_1,bl1_2,bl1_3, b1_ + (OFF_BL - OFF_BH)); \
    MMA3(0,0, bh0_0,bh0_1, bl0_0,bl0_1); \
    MMA3(0,1, bh0_2,bh0_3, bl0_2,bl0_3); \
    MMA3(0,2, bh1_0,bh1_1, bl1_0,bl1_1); \
    MMA3(0,3, bh1_2,bh1_3, bl1_2,bl1_3); \
    MMA3(1,0, bh0_0,bh0_1, bl0_0,bl0_1); \
    MMA3(1,1, bh0_2,bh0_3, bl0_2,bl0_3); \
    MMA3(1,2, bh1_0,bh1_1, bl1_0,bl1_1); \
    MMA3(1,3, bh1_2,bh1_3, bl1_2,bl1_3); \
    MMA3(2,0, bh0_0,bh0_1, bl0_0,bl0_1); \
    MMA3(2,1, bh0_2,bh0_3, bl0_2,bl0_3); \
    MMA3(2,2, bh1_0,bh1_1, bl1_0,bl1_1); \
    MMA3(2,3, bh1_2,bh1_3, bl1_2,bl1_3); \
    MMA3(3,0, bh0_0,bh0_1, bl0_0,bl0_1); \
    MMA3(3,1, bh0_2,bh0_3, bl0_2,bl0_3); \
    MMA3(3,2, bh1_0,bh1_1, bl1_0,bl1_1); \
    MMA3(3,3, bh1_2,bh1_3, bl1_2,bl1_3); \
} while(0)

// fp16 loads: A chunk hi/lo = 2 uint4/thread each; B likewise
#define LDGA(dsth, dstl, i_, k0_) do { \
    int row_ = (i_) >> 2, g_ = (i_) & 3; int gm_ = m0 + row_; \
    if (gm_ < MT) { \
        size_t so_ = (size_t)gm_ * EE + (k0_) + g_ * 8; \
        dsth = *(const uint4*)(Ah + so_); dstl = *(const uint4*)(Al + so_); \
    } else { dsth = make_uint4(0,0,0,0); dstl = make_uint4(0,0,0,0); } \
} while(0)
#define LDGB(dsth, dstl, i_, k0_) do { \
    int kr_ = (i_) >> 4, g_ = (i_) & 15; \
    size_t so_ = (size_t)((k0_) + kr_) * NCOLS + n0 + g_ * 8; \
    dsth = *(const uint4*)(Bh + so_); dstl = *(const uint4*)(Bl + so_); \
} while(0)
#define LDG_CHUNK(k0_) do { \
    LDGA(uah0, ual0, tid,       (k0_)); \
    LDGA(uah1, ual1, tid + 256, (k0_)); \
    LDGB(ubh0, ubl0, tid,       (k0_)); \
    LDGB(ubh1, ubl1, tid + 256, (k0_)); \
} while(0)

#define STS_A(uh, ul, i_) do { \
    int row_ = (i_) >> 2, g_ = (i_) & 3; \
    char* p_ = stgp + row_ * (A_STRIDE * 2) + g_ * 16; \
    *(uint4*)p_ = uh; *(uint4*)(p_ + OFF_AL) = ul; \
} while(0)
#define STS_B(uh, ul, i_) do { \
    int kr_ = (i_) >> 4, g_ = (i_) & 15; \
    char* p_ = stgp + OFF_BH + kr_ * (B_STRIDE * 2) + g_ * 16; \
    *(uint4*)p_ = uh; *(uint4*)(p_ + (OFF_BL - OFF_BH)) = ul; \
} while(0)

// MODE 0 scatter of one (row, col-pair): q/v natural 4B pairs, k transposed 2B
#define SCAT0(r_, col_, v0, v1) do { \
    int bb_ = (r_) / NT, nn_ = (r_) - bb_ * NT; \
    int which_ = (col_) / EE, cc_ = (col_) - which_ * EE; \
    int hh_ = cc_ >> 6, dd_ = cc_ & 63; \
    int bh_ = bb_ * NH + hh_; \
    uint32_t hi_ = f2h2((v0), (v1)); \
    uint32_t lo_ = f2h2((v0) - rn16(v0), (v1) - rn16(v1)); \
    if (which_ == 1) { \
        size_t o0_ = ((size_t)(bh_ * HD + dd_)) * NTP + nn_; \
        size_t o1_ = ((size_t)(bh_ * HD + dd_ + 1)) * NTP + nn_; \
        *(unsigned short*)((char*)g_kth + o0_*2) = (unsigned short)(hi_ & 0xFFFF); \
        *(unsigned short*)((char*)g_kth + o1_*2) = (unsigned short)(hi_ >> 16); \
        *(unsigned short*)((char*)g_ktl + o0_*2) = (unsigned short)(lo_ & 0xFFFF); \
        *(unsigned short*)((char*)g_ktl + o1_*2) = (unsigned short)(lo_ >> 16); \
    } else { \
        __half* bh_p = (which_ == 0) ? g_qh : g_vh; \
        __half* bl_p = (which_ == 0) ? g_ql : g_vl; \
        size_t o_ = (((size_t)bh_ * NT + nn_)) * HD + dd_; \
        *(uint32_t*)((char*)bh_p + o_*2) = hi_; \
        *(uint32_t*)((char*)bl_p + o_*2) = lo_; \
    } \
} while(0)

#define STORE2(r_, col_, v0, v1) do { \
    if (MODE == 1) { \
        float2 o_; o_.x = (v0) + bias[(col_)]; o_.y = (v1) + bias[(col_)+1]; \
        *(float2*)(Cout + (size_t)(r_) * EE + (col_)) = o_; \
    } else { \
        SCAT0(r_, col_, v0, v1); \
    } \
} while(0)

#define STORE_TILE(m,n) do { \
    int r_ = m0 + wm0 + (m)*16 + (lane >> 2); \
    int cb_ = n0 + wn0 + (n)*8 + (lane & 3) * 2; \
    if (r_ < MT)     STORE2(r_,     cb_, c##m##n##_0, c##m##n##_1); \
    if (r_ + 8 < MT) STORE2(r_ + 8, cb_, c##m##n##_2, c##m##n##_3); \
} while(0)

template<int MODE>
__global__ __launch_bounds__(256, 1)
void gemm_mma(const float* __restrict__ bias, float* __restrict__ Cout)
{
    constexpr int NCOLS = (MODE == 0) ? 3 * EE : EE;
    // data pointers resolved in DEVICE code (legal symbol references)
    const __half* __restrict__ Ah = (MODE == 0) ? g_xh : g_ch;
    const __half* __restrict__ Al = (MODE == 0) ? g_xl : g_cl;
    const __half* __restrict__ Bh = (MODE == 0) ? g_wh : g_ph;
    const __half* __restrict__ Bl = (MODE == 0) ? g_wl : g_pl;

    extern __shared__ char smem_raw[];
    const uint32_t sb = smem_u32(smem_raw);
    const int tid = threadIdx.x;
    const int lane = tid & 31, wid = tid >> 5;
    const int m0 = blockIdx.y * 128, n0 = blockIdx.x * 128;
    const int wm0 = (wid >> 2) * 64, wn0 = (wid & 3) * 32;
    const int r15 = lane & 15, h16 = lane >> 4;

    DECL_ACC(0,0); DECL_ACC(0,1); DECL_ACC(0,2); DECL_ACC(0,3);
    DECL_ACC(1,0); DECL_ACC(1,1); DECL_ACC(1,2); DECL_ACC(1,3);
    DECL_ACC(2,0); DECL_ACC(2,1); DECL_ACC(2,2); DECL_ACC(2,3);
    DECL_ACC(3,0); DECL_ACC(3,1); DECL_ACC(3,2); DECL_ACC(3,3);

    uint4 uah0, uah1, ual0, ual1, ubh0, ubh1, ubl0, ubl1;
    LDG_CHUNK(0);

    const int NC = 24;
#pragma unroll 1
    for (int c = 0; c < NC; c++) {
        {
            char* stgp = smem_raw + (c & 1) * GEMM_STG;
            STS_A(uah0, ual0, tid);
            STS_A(uah1, ual1, tid + 256);
            STS_B(ubh0, ubl0, tid);
            STS_B(ubh1, ubl1, tid + 256);
        }
        __syncthreads();
        if (c + 1 < NC) LDG_CHUNK((c + 1) * 32);
        const uint32_t stg = sb + (c & 1) * GEMM_STG;
        KSTEP(0);
        KSTEP(1);
        __syncthreads();
    }

    STORE_TILE(0,0); STORE_TILE(0,1); STORE_TILE(0,2); STORE_TILE(0,3);
    STORE_TILE(1,0); STORE_TILE(1,1); STORE_TILE(1,2); STORE_TILE(1,3);
    STORE_TILE(2,0); STORE_TILE(2,1); STORE_TILE(2,2); STORE_TILE(2,3);
    STORE_TILE(3,0); STORE_TILE(3,1); STORE_TILE(3,2); STORE_TILE(3,3);
}

// ===========================================================================
// Fused attention with mma.sync GEMMs; pre-split fp16 inputs, grid 1536
// (one CTA per (b,h) x i-half). Layouts as round 12.
// ===========================================================================
#define SKLD 272
#define SVLD 72
#define SQLD 72
#define SPLD 272
#define SSLD 272
#define AO_KSH 0
#define AO_KSL 34816
#define AO_VSH 69632
#define AO_VSL 108800
#define AO_QSH 147968
#define AO_QSL 152576
#define AO_PH  157184
#define AO_PL  174592
#define AO_S   192000
#define ATT_SMEM_BYTES 226816

#define LOADQ(ks) \
    LDSM4(qh##ks##_0,qh##ks##_1,qh##ks##_2,qh##ks##_3, qa_ + (ks)*32); \
    LDSM4(ql##ks##_0,ql##ks##_1,ql##ks##_2,ql##ks##_3, qa_ + (ks)*32 + (AO_QSL - AO_QSH))

#define SCORE_K(ks) do { \
    uint32_t kh0,kh1,kh2,kh3, kl0,kl1,kl2,kl3; \
    uint32_t ka_ = sb + AO_KSH + (uint32_t)(((ks)*16 + r15) * SKLD + n0 + h16*8) * 2; \
    LDSM4T(kh0,kh1,kh2,kh3, ka_); \
    LDSM4T(kl0,kl1,kl2,kl3, ka_ + (AO_KSL - AO_KSH)); \
    MMA_S(e0,e1,e2,e3, qh##ks##_0,qh##ks##_1,qh##ks##_2,qh##ks##_3, kh0,kh1); \
    MMA_S(e0,e1,e2,e3, qh##ks##_0,qh##ks##_1,qh##ks##_2,qh##ks##_3, kl0,kl1); \
    MMA_S(e0,e1,e2,e3, ql##ks##_0,ql##ks##_1,ql##ks##_2,ql##ks##_3, kh0,kh1); \
    MMA_S(f0,f1,f2,f3, qh##ks##_0,qh##ks##_1,qh##ks##_2,qh##ks##_3, kh2,kh3); \
    MMA_S(f0,f1,f2,f3, qh##ks##_0,qh##ks##_1,qh##ks##_2,qh##ks##_3, kl2,kl3); \
    MMA_S(f0,f1,f2,f3, ql##ks##_0,ql##ks##_1,ql##ks##_2,ql##ks##_3, kh2,kh3); \
} while(0)

__global__ __launch_bounds__(256, 1)
void attn_k(const float* __restrict__ rk_v, const float* __restrict__ rk_h,
            const float* __restrict__ rv_v, const float* __restrict__ rv_h)
{
    extern __shared__ char smem_raw[];
    char* smr = smem_raw;
    const uint32_t sb = smem_u32(smem_raw);
    const int bh = blockIdx.x >> 1;
    const int half = blockIdx.x & 1;
    const int tid = threadIdx.x;
    const int w = tid >> 5, lane = tid & 31;
    const int r15 = lane & 15, h16 = lane >> 4;
    const int b = bh / NH, h = bh - b*NH;

    // ---- phase 1: uint4 copies of pre-split K^T / V ----
    for (int i = tid; i < 64*25; i += 256) {           // K^T: 64 rows x 25 chunks
        int d = i / 25, c8 = i - d * 25;
        const uint4 vh = *(const uint4*)(g_kth + ((size_t)(bh*HD + d))*NTP + c8*8);
        const uint4 vl = *(const uint4*)(g_ktl + ((size_t)(bh*HD + d))*NTP + c8*8);
        char* p = smr + AO_KSH + (size_t)(d*SKLD + c8*8) * 2;
        *(uint4*)p = vh;
        *(uint4*)(p + (AO_KSL - AO_KSH)) = vl;
    }
    for (int i = tid; i < NT*8; i += 256) {            // V: 197 rows x 8 chunks
        int row = i >> 3, g = i & 7;
        const uint4 vh = *(const uint4*)(g_vh + ((size_t)(bh*NT + row))*HD + g*8);
        const uint4 vl = *(const uint4*)(g_vl + ((size_t)(bh*NT + row))*HD + g*8);
        char* p = smr + AO_VSH + (size_t)(row*SVLD + g*8) * 2;
        *(uint4*)p = vh;
        *(uint4*)(p + (AO_VSL - AO_VSH)) = vl;
    }
    // zero V pad rows 257..271 (PV reads them)
    for (int i = tid; i < (15*SVLD*2)/4; i += 256) {
        *(uint32_t*)(smr + AO_VSH + 257*SVLD*2 + i*4) = 0;
        *(uint32_t*)(smr + AO_VSL + 257*SVLD*2 + i*4) = 0;
    }
    __syncthreads();   // copies (K^T cols <=199) before table writes (cols 197+)

    // ---- phase 2: rel-pos tables (fp32 -> hi/lo, tiny) ----
    for (int i = tid; i < TROWS*HD; i += 256) {
        int t = i >> 6, d = i & 63;
        float v = rk_v[i], hv = rn16(v);
        size_t o = (size_t)(d*SKLD + 197 + t) * 2;
        sth(smr + AO_KSH + o, v); sth(smr + AO_KSL + o, v - hv);
        float v2 = rk_h[i], hv2 = rn16(v2);
        size_t o2 = (size_t)(d*SKLD + 227 + t) * 2;
        sth(smr + AO_KSH + o2, v2); sth(smr + AO_KSL + o2, v2 - hv2);
        float u = rv_v[i], hu = rn16(u);
        size_t p = (size_t)((197 + t)*SVLD + d) * 2;
        sth(smr + AO_VSH + p, u); sth(smr + AO_VSL + p, u - hu);
        float u2 = rv_h[i], hu2 = rn16(u2);
        size_t p2 = (size_t)((227 + t)*SVLD + d) * 2;
        sth(smr + AO_VSH + p2, u2); sth(smr + AO_VSL + p2, u2 - hu2);
    }
    __syncthreads();

    const int iBeg = half * 128;
    const int iEnd = half ? NT : 128;
    for (int i0 = iBeg; i0 < iEnd; i0 += 32) {
        // ---- Q block: uint4 copies ----
        for (int i = tid; i < 32*8; i += 256) {
            int r = i >> 3, g = i & 7;
            int gi = i0 + r;
            uint4 vh = make_uint4(0,0,0,0), vl = make_uint4(0,0,0,0);
            if (gi < NT) {
                vh = *(const uint4*)(g_qh + ((size_t)(bh*NT + gi))*HD + g*8);
                vl = *(const uint4*)(g_ql + ((size_t)(bh*NT + gi))*HD + g*8);
            }
            char* p = smr + AO_QSH + (size_t)(r*SQLD + g*8) * 2;
            *(uint4*)p = vh;
            *(uint4*)(p + (AO_QSL - AO_QSH)) = vl;
        }
        __syncthreads();

        // ---- score GEMM ----
        {
            const int am0 = (w & 1) * 16;
            uint32_t qa_ = sb + AO_QSH + (uint32_t)((am0 + r15) * SQLD + h16*8) * 2;
            uint32_t qh0_0,qh0_1,qh0_2,qh0_3, qh1_0,qh1_1,qh1_2,qh1_3;
            uint32_t qh2_0,qh2_1,qh2_2,qh2_3, qh3_0,qh3_1,qh3_2,qh3_3;
            uint32_t ql0_0,ql0_1,ql0_2,ql0_3, ql1_0,ql1_1,ql1_2,ql1_3;
            uint32_t ql2_0,ql2_1,ql2_2,ql2_3, ql3_0,ql3_1,ql3_2,ql3_3;
            LOADQ(0); LOADQ(1); LOADQ(2); LOADQ(3);
            float* S = (float*)(smr + AO_S);
#pragma unroll 1
            for (int p = (w >> 1); p < 17; p += 4) {
                int n0 = p * 16;
                float e0=0,e1=0,e2=0,e3=0, f0=0,f1=0,f2=0,f3=0;
                SCORE_K(0); SCORE_K(1); SCORE_K(2); SCORE_K(3);
                float* sr0 = S + (am0 + (lane >> 2)) * SSLD + n0 + (lane & 3) * 2;
                *(float2*)sr0 = make_float2(e0, e1);
                *(float2*)(sr0 + 8*SSLD) = make_float2(e2, e3);
                *(float2*)(sr0 + 8) = make_float2(f0, f1);
                *(float2*)(sr0 + 8*SSLD + 8) = make_float2(f2, f3);
            }
        }
        __syncthreads();

        // ---- softmax + rel-pos bins ----
        {
            float* S = (float*)(smr + AO_S);
            for (int rr = 0; rr < 4; rr++) {
                int r = w*4 + rr;
                int gi = i0 + r;
                if (gi >= NT) continue;
                float* srow = S + r*SSLD;
                int gvi = (gi > 0) ? (gi-1) / GRID14 : 0;
                int ghi = (gi > 0) ? (gi-1) % GRID14 : 0;

                float sv[7];
                float mx = -1e30f;
#pragma unroll
                for (int jj = 0; jj < 7; jj++) {
                    int j = lane + jj*32;
                    float s = -1e30f;
                    if (j < NT) {
                        int tv = 0, th = 0;
                        if (gi > 0 && j > 0) {
                            tv = (j-1)/GRID14 - gvi + 15;
                            th = (j-1)%GRID14 - ghi + 15;
                        }
                        s = (srow[j] + srow[197+tv] + srow[227+th]) * 0.125f;
                    }
                    sv[jj] = s;
                    mx = fmaxf(mx, s);
                }
#pragma unroll
                for (int o = 16; o > 0; o >>= 1) mx = fmaxf(mx, __shfl_xor_sync(0xFFFFFFFFu, mx, o));
                float sum = 0.f;
#pragma unroll
                for (int jj = 0; jj < 7; jj++) { float e = __expf(sv[jj]-mx); sv[jj] = e; sum += e; }
#pragma unroll
                for (int o = 16; o > 0; o >>= 1) sum += __shfl_xor_sync(0xFFFFFFFFu, sum, o);
                float inv = 1.f / sum;
#pragma unroll
                for (int jj = 0; jj < 7; jj++) {
                    int j = lane + jj*32;
                    if (j < NT) srow[j] = sv[jj]*inv;
                }
                __syncwarp();
                if (lane < TROWS) { srow[197+lane] = 0.f; srow[227+lane] = 0.f; }
                __syncwarp();
                if (gi == 0) {
                    if (lane == 0) { srow[197] = 1.f; srow[227] = 1.f; }
                } else {
                    if (lane < 14) {
                        float R = 0.f;
#pragma unroll
                        for (int c = 0; c < 14; c++) R += srow[1 + lane*14 + c];
                        srow[197 + (lane - gvi + 15)] = R;
                    } else if (lane == 14) {
                        float p0 = srow[0];
                        srow[197] = p0; srow[227] = p0;
                    } else if (lane >= 16 && lane < 30) {
                        int c = lane - 16;
                        float Cc = 0.f;
#pragma unroll
                        for (int g = 0; g < 14; g++) Cc += srow[1 + g*14 + c];
                        srow[227 + (c - ghi + 15)] = Cc;
                    }
                }
                __syncwarp();
            }
        }
        __syncthreads();

        // ---- convert P to hi/lo ----
        {
            float* S = (float*)(smr + AO_S);
            for (int idx = tid; idx < 32 * SPLD; idx += 256) {
                int row = idx / SPLD, col = idx - row * SPLD;
                float v = (col < 257) ? S[row * SSLD + col] : 0.f;
                float hv = rn16(v);
                sth(smr + AO_PH + (size_t)idx * 2, v);
                sth(smr + AO_PL + (size_t)idx * 2, v - hv);
            }
        }
        __syncthreads();

        // ---- PV GEMM; epilogue writes ctx as fp16 hi/lo ----
        {
            const int am0 = (w & 1) * 16;
            const int n0v = (w >> 1) * 16;
            float u0=0,u1=0,u2=0,u3=0, t0=0,t1=0,t2=0,t3=0;
#pragma unroll 1
            for (int ks = 0; ks < 17; ks++) {
                uint32_t pa0,pa1,pa2,pa3, pb0,pb1,pb2,pb3;
                uint32_t vh0,vh1,vh2,vh3, vl0,vl1,vl2,vl3;
                uint32_t pa_ = sb + AO_PH + (uint32_t)((am0 + r15) * SPLD + ks*16 + h16*8) * 2;
                LDSM4(pa0,pa1,pa2,pa3, pa_);
                LDSM4(pb0,pb1,pb2,pb3, pa_ + (AO_PL - AO_PH));
                uint32_t va_ = sb + AO_VSH + (uint32_t)((ks*16 + r15) * SVLD + n0v + h16*8) * 2;
                LDSM4T(vh0,vh1,vh2,vh3, va_);
                LDSM4T(vl0,vl1,vl2,vl3, va_ + (AO_VSL - AO_VSH));
                MMA_S(u0,u1,u2,u3, pa0,pa1,pa2,pa3, vh0,vh1);
                MMA_S(u0,u1,u2,u3, pa0,pa1,pa2,pa3, vl0,vl1);
                MMA_S(u0,u1,u2,u3, pb0,pb1,pb2,pb3, vh0,vh1);
                MMA_S(t0,t1,t2,t3, pa0,pa1,pa2,pa3, vh2,vh3);
                MMA_S(t0,t1,t2,t3, pa0,pa1,pa2,pa3, vl2,vl3);
                MMA_S(t0,t1,t2,t3, pb0,pb1,pb2,pb3, vh2,vh3);
            }
            int gi0 = i0 + am0 + (lane >> 2);
            int cc = n0v + (lane & 3) * 2;
            if (gi0 < NT) {
                size_t base = ((size_t)(b*NT + gi0))*EE + h*HD;
                *(uint32_t*)((char*)g_ch + (base + cc)*2)     = f2h2(u0, u1);
                *(uint32_t*)((char*)g_cl + (base + cc)*2)     = f2h2(u0 - rn16(u0), u1 - rn16(u1));
                *(uint32_t*)((char*)g_ch + (base + cc + 8)*2) = f2h2(t0, t1);
                *(uint32_t*)((char*)g_cl + (base + cc + 8)*2) = f2h2(t0 - rn16(t0), t1 - rn16(t1));
            }
            if (gi0 + 8 < NT) {
                size_t base = ((size_t)(b*NT + gi0 + 8))*EE + h*HD;
                *(uint32_t*)((char*)g_ch + (base + cc)*2)     = f2h2(u2, u3);
                *(uint32_t*)((char*)g_cl + (base + cc)*2)     = f2h2(u2 - rn16(u2), u3 - rn16(u3));
                *(uint32_t*)((char*)g_ch + (base + cc + 8)*2) = f2h2(t2, t3);
                *(uint32_t*)((char*)g_cl + (base + cc + 8)*2) = f2h2(t2 - rn16(t2), t3 - rn16(t3));
            }
        }
        __syncthreads();
    }
}

// ---------------------------------------------------------------------------
extern "C" void kernel_launch(void* const* d_in, const int* in_sizes, int n_in,
                              void* d_out, int out_size)
{
    const float* x     = (const float*)d_in[0];
    const float* wq    = (const float*)d_in[1];
    const float* wk    = (const float*)d_in[2];
    const float* wv    = (const float*)d_in[3];
    const float* wproj = (const float*)d_in[4];
    const float* bproj = (const float*)d_in[5];
    const float* rk_v  = (const float*)d_in[6];
    const float* rk_h  = (const float*)d_in[7];
    const float* rv_v  = (const float*)d_in[8];
    const float* rv_h  = (const float*)d_in[9];
    float* out = (float*)d_out;

    cudaFuncSetAttribute(gemm_mma<0>, cudaFuncAttributeMaxDynamicSharedMemorySize, GEMM_SMEM);
    cudaFuncSetAttribute(gemm_mma<1>, cudaFuncAttributeMaxDynamicSharedMemorySize, GEMM_SMEM);
    cudaFuncSetAttribute(attn_k, cudaFuncAttributeMaxDynamicSharedMemorySize, ATT_SMEM_BYTES);

    split_x_k<<<(MT*EE/4 + 255)/256, 256>>>(x);
    split_wqkv_k<<<(EE*576 + 255)/256, 256>>>(wq, wk, wv);
    split_wp_k<<<(EE*EE/4 + 255)/256, 256>>>(wproj);

    dim3 g1(3*EE/128, (MT + 127)/128);
    gemm_mma<0><<<g1, 256, GEMM_SMEM>>>(nullptr, nullptr);

    attn_k<<<NBH*2, 256, ATT_SMEM_BYTES>>>(rk_v, rk_h, rv_v, rv_h);

    dim3 g2(EE/128, (MT + 127)/128);
    gemm_mma<1><<<g2, 256, GEMM_SMEM>>>(bproj, out);
}